// round 14
// baseline (speedup 1.0000x reference)
#include <cuda_runtime.h>
#include <cuda_bf16.h>
#include <cstdint>
#include <math.h>

#define BB   2
#define CC   48
#define HH   128
#define WW   256
#define HWW  (HH*WW)          // 32768
#define C3   144
#define C2   96
#define NH   3
#define BSTR 140              // qkv B row stride (u32)
#define ASTR 104              // A tile row stride (bf16)
#define DSTR 268              // dilated B row stride (u32): 256 px + 12 halo; 268%32==12
#define DBUF (48*DSTR)        // u32 per dilated B buffer
#define ATILE (48*ASTR)       // bf16 per dilated A buffer
#define VSTR 260              // epilogue V row stride (u32)

// ---------------- scratch (static device globals; no allocation) ----------------
__device__ __nv_bfloat16  g_pre_bf [2][BB][C3][HWW];   // bf16 qkv after LN+1x1
__device__ __nv_bfloat16  g_kb     [2][BB][CC][HWW];   // bf16 K after dw, [c][px]
__device__ uint32_t       g_vp     [2][BB][24][HWW];   // pair-packed bf16 V after dw
__device__ uint32_t       g_xp     [BB][CC][HWW];      // channel-pair-packed bf16 [Q_l;Q_r]
__device__ __nv_bfloat16  g_qb     [BB][CC][HWW];      // bf16 fused dilated+convQ output
__device__ __nv_bfloat16  g_wbf    [27][64][C2];       // folded bf16 dilated weights
__device__ __nv_bfloat16  g_wq     [2][C3][CC];        // bf16 W' = W * diag(lnw)
__device__ float          g_S      [2*C3];             // rowsum of W'
__device__ float          g_Cb     [2*C3];             // W@lnb + bias
__device__ float          g_mu     [2][BB][HWW];
__device__ float          g_rs     [2][BB][HWW];
__device__ float          g_beff   [CC];
__device__ float          g_dpart  [2*BB*NH*16*256];
__device__ float          g_nsq    [2][BB][NH][16][2][16];
__device__ __nv_bfloat16  g_Mbf    [2*BB][CC*CC];

__device__ __forceinline__ uint32_t smem_u32(const void* p) {
    uint32_t a;
    asm("{ .reg .u64 t; cvta.to.shared.u64 t, %1; cvt.u32.u64 %0, t; }" : "=r"(a) : "l"(p));
    return a;
}
__device__ __forceinline__ void ldsm4(uint32_t* r, uint32_t addr) {
    asm volatile("ldmatrix.sync.aligned.m8n8.x4.shared.b16 {%0,%1,%2,%3}, [%4];"
        : "=r"(r[0]), "=r"(r[1]), "=r"(r[2]), "=r"(r[3]) : "r"(addr));
}
__device__ __forceinline__ void mma16816(float* c, const uint32_t* a, uint32_t b0, uint32_t b1) {
    asm volatile("mma.sync.aligned.m16n8k16.row.col.f32.bf16.bf16.f32 "
        "{%0,%1,%2,%3}, {%4,%5,%6,%7}, {%8,%9}, {%0,%1,%2,%3};"
        : "+f"(c[0]), "+f"(c[1]), "+f"(c[2]), "+f"(c[3])
        : "r"(a[0]), "r"(a[1]), "r"(a[2]), "r"(a[3]), "r"(b0), "r"(b1));
}
__device__ __forceinline__ uint32_t pack_bf2(float a, float b) {
    return (uint32_t)__bfloat16_as_ushort(__float2bfloat16_rn(a))
         | ((uint32_t)__bfloat16_as_ushort(__float2bfloat16_rn(b)) << 16);
}
__device__ __forceinline__ void st_bf2(__nv_bfloat16* p, float a, float b) {
    *reinterpret_cast<uint32_t*>(p) = pack_bf2(a, b);
}
__device__ __forceinline__ float bf_lo(uint32_t u) {
    return __bfloat162float(__ushort_as_bfloat16((unsigned short)(u & 0xFFFF)));
}
__device__ __forceinline__ float bf_hi(uint32_t u) {
    return __bfloat162float(__ushort_as_bfloat16((unsigned short)(u >> 16)));
}

// ---------------- merged prelude: W' + fold_w + fold_b + S/C + LN stats ----------------
__global__ void k_misc(const float* __restrict__ wl, const float* __restrict__ wr,
                       const float* __restrict__ cqw, const float* __restrict__ cqb,
                       const float* __restrict__ d0w, const float* __restrict__ d1w,
                       const float* __restrict__ d2w,
                       const float* __restrict__ d0b, const float* __restrict__ d1b,
                       const float* __restrict__ d2b,
                       const float* __restrict__ ln1w, const float* __restrict__ ln1b,
                       const float* __restrict__ ln2w, const float* __restrict__ ln2b,
                       const float* __restrict__ qbl, const float* __restrict__ qbr,
                       const float* __restrict__ xl, const float* __restrict__ xr) {
    int blk = blockIdx.x, tid = threadIdx.x;
    __shared__ float smf[192];
    if (blk < 54) {                               // W' = W * diag(lnw) -> bf16
        int i = blk*256 + tid;
        int s = i / (C3*CC), r = i - s*(C3*CC);
        int c = r % CC;
        const float* lw = s ? ln2w : ln1w;
        reinterpret_cast<__nv_bfloat16*>(g_wq)[i] =
            __float2bfloat16_rn((s ? wr : wl)[r] * lw[c]);
    } else if (blk < 198) {                       // fold_w: 144 blocks (o, d)
        int idx = blk - 54;
        int o = idx % CC, d = idx / CC;
        const float* dw = (d == 0) ? d0w : (d == 1) ? d1w : d2w;
        float* qr = smf;
        for (int j = tid; j < C2; j += 256)
            qr[j] = cqw[o*(3*C2) + d*C2 + j];
        __syncthreads();
        for (int ik = tid; ik < C2*9; ik += 256) {
            float acc = 0.f;
            for (int j = 0; j < C2; ++j)
                acc += qr[j] * dw[j*(C2*9) + ik];
            int i = ik / 9, kk = ik - i*9;
            g_wbf[d*9 + kk][o][i] = __float2bfloat16_rn(acc);
        }
    } else if (blk == 198) {                      // fold_b (dilated bias)
        if (tid < 192) {
            int o = tid >> 2, q = tid & 3;
            float acc = 0.f;
            for (int j = q*72; j < q*72 + 72; ++j) {
                int dd = j / 96, jj = j - dd*96;
                const float* bp = (dd == 0) ? d0b : (dd == 1) ? d1b : d2b;
                acc += cqw[o*288 + j] * bp[jj];
            }
            smf[tid] = acc;
        }
        __syncthreads();
        if (tid < CC)
            g_beff[tid] = cqb[tid] + smf[tid*4] + smf[tid*4+1] + smf[tid*4+2] + smf[tid*4+3];
    } else if (blk == 199) {                      // S/C per branch
        for (int i = tid; i < 2*C3; i += 256) {
            int s = i / C3, o = i - s*C3;
            const float* w  = s ? wr : wl;
            const float* lw = s ? ln2w : ln1w;
            const float* lb = s ? ln2b : ln1b;
            float S = 0.f, C = 0.f;
            for (int c = 0; c < CC; ++c) {
                float wv = w[o*CC + c];
                S += wv * lw[c];
                C += wv * lb[c];
            }
            g_S[i]  = S;
            g_Cb[i] = C + (s ? qbr : qbl)[o];
        }
    } else {                                      // LN stats: 512 blocks
        int blk2 = blk - 200;
        int branch = blk2 >> 8, rem = blk2 & 255;
        int b = rem >> 7, p0 = (rem & 127)*256;
        const float* x = (branch ? xr : xl) + b*CC*HWW;
        int p = p0 + tid;
        float mu = 0.f;
        #pragma unroll
        for (int c = 0; c < CC; ++c) mu += x[c*HWW + p];
        mu *= (1.f/CC);
        float var = 0.f;
        #pragma unroll
        for (int c = 0; c < CC; ++c) { float t = x[c*HWW + p] - mu; var += t*t; }
        g_mu[branch][b][p] = mu;
        g_rs[branch][b][p] = rsqrtf(var*(1.f/CC) + 1e-6f);
    }
}

// ---------------- 1x1 qkv GEMM on raw x, LN folded into epilogue ----------------
__global__ void __launch_bounds__(288) k_qkv(const float* __restrict__ xl,
                                             const float* __restrict__ xr) {
    __shared__ uint32_t Bs[24*BSTR];
    __shared__ __align__(16) __nv_bfloat16 As[C3*CC];
    __shared__ float Ss[C3], Cs[C3], mus[128], rss[128];
    int p0 = blockIdx.x*128, b = blockIdx.y, branch = blockIdx.z;
    int tid = threadIdx.x, lane = tid & 31, wid = tid >> 5;
    const float* x = (branch ? xr : xl) + b*CC*HWW;
    {
        const uint4* src = reinterpret_cast<const uint4*>(&g_wq[branch][0][0]);
        uint4* dst = reinterpret_cast<uint4*>(As);
        for (int i = tid; i < C3*CC/8; i += 288) dst[i] = src[i];
        for (int i = tid; i < C3; i += 288) { Ss[i] = g_S[branch*C3 + i]; Cs[i] = g_Cb[branch*C3 + i]; }
        for (int i = tid; i < 128; i += 288) {
            mus[i] = g_mu[branch][b][p0 + i];
            rss[i] = g_rs[branch][b][p0 + i];
        }
        for (int i = tid; i < 24*128; i += 288) {
            int kp = i >> 7, p = i & 127;
            Bs[kp*BSTR + p] = pack_bf2(x[(2*kp)*HWW + p0 + p], x[(2*kp+1)*HWW + p0 + p]);
        }
    }
    __syncthreads();
    uint32_t smbA = smem_u32(As);
    int r0 = lane >> 2, cb = (lane & 3)*2;
    int oc0 = wid*16 + r0, oc1 = oc0 + 8;
    float S0 = Ss[oc0], S1 = Ss[oc1];
    float C0 = Cs[oc0], C1 = Cs[oc1];
    __nv_bfloat16* o0 = &g_pre_bf[branch][b][oc0][p0];
    __nv_bfloat16* o1 = &g_pre_bf[branch][b][oc1][p0];
    #pragma unroll
    for (int half = 0; half < 2; ++half) {
        float acc[4][2][4];
        #pragma unroll
        for (int np = 0; np < 4; ++np)
            #pragma unroll
            for (int f = 0; f < 2; ++f)
                #pragma unroll
                for (int q = 0; q < 4; ++q) acc[np][f][q] = 0.f;
        #pragma unroll
        for (int kb = 0; kb < 3; ++kb) {
            uint32_t a[4];
            int row = wid*16 + (lane & 15);
            ldsm4(a, smbA + (uint32_t)(row*CC + kb*16 + ((lane >> 4) << 3))*2u);
            const uint32_t* b_lo = Bs + (kb*8 + (lane & 3))*BSTR + (lane >> 2) + half*64;
            const uint32_t* b_hi = b_lo + 4*BSTR;
            #pragma unroll
            for (int np = 0; np < 4; ++np) {
                uint32_t b0 = b_lo[np*16], b1 = b_hi[np*16];
                uint32_t b2 = b_lo[np*16 + 8], b3 = b_hi[np*16 + 8];
                mma16816(acc[np][0], a, b0, b1);
                mma16816(acc[np][1], a, b2, b3);
            }
        }
        #pragma unroll
        for (int np = 0; np < 4; ++np)
            #pragma unroll
            for (int f = 0; f < 2; ++f) {
                int c = half*64 + np*16 + f*8 + cb;
                float m0 = mus[c], r0v = rss[c];
                float m1 = mus[c+1], r1v = rss[c+1];
                st_bf2(o0 + c, r0v*(acc[np][f][0] - m0*S0) + C0,
                               r1v*(acc[np][f][1] - m1*S0) + C0);
                st_bf2(o1 + c, r0v*(acc[np][f][2] - m0*S1) + C1,
                               r1v*(acc[np][f][3] - m1*S1) + C1);
            }
    }
}

// ---------------- depthwise 3x3, channel-pair blocks, 8-row tiles ----------------
__global__ void __launch_bounds__(512) k_dw(const float* __restrict__ wl, const float* __restrict__ bl,
                                            const float* __restrict__ wr, const float* __restrict__ brb) {
    int z = blockIdx.z; int branch = z >> 1, b = z & 1;
    int chp = blockIdx.y;                  // 0..71 (channel pair)
    int c0 = 2*chp;
    int y0 = blockIdx.x * 8;
    __shared__ __align__(16) float rows[2][10][264];
    const float* wbase = (branch == 0 ? wl : wr);
    const float* bbase = (branch == 0 ? bl : brb);
    int tid = threadIdx.x;

    for (int idx = tid; idx < 2*10*64; idx += 512) {
        int cc = idx / 640, rem = idx - cc*640;
        int r = rem >> 6, c4 = rem & 63;
        int gy = y0 - 1 + r;
        float4 f = make_float4(0.f, 0.f, 0.f, 0.f);
        if (gy >= 0 && gy < HH) {
            const __nv_bfloat16* in = &g_pre_bf[branch][b][c0 + cc][0];
            uint2 v = *reinterpret_cast<const uint2*>(&in[gy*WW + c4*4]);
            f.x = bf_lo(v.x); f.y = bf_hi(v.x);
            f.z = bf_lo(v.y); f.w = bf_hi(v.y);
        }
        *reinterpret_cast<float4*>(&rows[cc][r][4 + 4*c4]) = f;
    }
    if (tid < 20) { int cc = tid / 10, r = tid % 10; rows[cc][r][3] = 0.f; rows[cc][r][260] = 0.f; }
    __syncthreads();

    int r  = tid >> 6;                 // 0..7
    int x0 = (tid & 63) * 4;
    float out[2][4];
    #pragma unroll
    for (int cc = 0; cc < 2; ++cc) {
        const float* w = wbase + (c0 + cc)*9;
        float bias = bbase[c0 + cc];
        float a0 = bias, a1 = bias, a2 = bias, a3 = bias;
        #pragma unroll
        for (int ky = 0; ky < 3; ++ky) {
            const float* rp = &rows[cc][r + ky][3 + x0];
            float v0 = rp[0];
            float4 vm = *reinterpret_cast<const float4*>(rp + 1);
            float v5 = rp[5];
            float w0 = w[ky*3], w1 = w[ky*3+1], w2 = w[ky*3+2];
            a0 += w0*v0   + w1*vm.x + w2*vm.y;
            a1 += w0*vm.x + w1*vm.y + w2*vm.z;
            a2 += w0*vm.y + w1*vm.z + w2*vm.w;
            a3 += w0*vm.z + w1*vm.w + w2*v5;
        }
        out[cc][0] = a0; out[cc][1] = a1; out[cc][2] = a2; out[cc][3] = a3;
    }
    int px = (y0 + r)*WW + x0;
    if (chp < 24) {              // Q pair -> g_xp (channel-pair packed)
        uint4 u;
        u.x = pack_bf2(out[0][0], out[1][0]); u.y = pack_bf2(out[0][1], out[1][1]);
        u.z = pack_bf2(out[0][2], out[1][2]); u.w = pack_bf2(out[0][3], out[1][3]);
        *reinterpret_cast<uint4*>(&g_xp[b][branch*24 + chp][px]) = u;
    } else if (chp < 48) {       // K -> plain bf16 [c][px]
        int kc = c0 - CC;
        uint2 u0, u1;
        u0.x = pack_bf2(out[0][0], out[0][1]); u0.y = pack_bf2(out[0][2], out[0][3]);
        u1.x = pack_bf2(out[1][0], out[1][1]); u1.y = pack_bf2(out[1][2], out[1][3]);
        *reinterpret_cast<uint2*>(&g_kb[branch][b][kc][px])     = u0;
        *reinterpret_cast<uint2*>(&g_kb[branch][b][kc + 1][px]) = u1;
    } else {                     // V pair -> g_vp
        uint4 u;
        u.x = pack_bf2(out[0][0], out[1][0]); u.y = pack_bf2(out[0][1], out[1][1]);
        u.z = pack_bf2(out[0][2], out[1][2]); u.w = pack_bf2(out[0][3], out[1][3]);
        *reinterpret_cast<uint4*>(&g_vp[branch][b][chp - 48][px]) = u;
    }
}

// ---------------- fused dilated convs + convQ (unchanged from round 13) ----------------
__global__ void __launch_bounds__(256, 2) k_dilated_mma() {
    extern __shared__ __align__(16) uint32_t smx[];
    uint32_t* Bs = smx;
    __nv_bfloat16* As = reinterpret_cast<__nv_bfloat16*>(smx + 2*DBUF);
    uint32_t smbB = smem_u32(Bs), smbA = smem_u32(As);
    int y = blockIdx.x, b = blockIdx.y;
    int tid = threadIdx.x, lane = tid & 31, nq = tid >> 5;
    const uint32_t* xp = &g_xp[b][0][0];

    float acc[3][2][2][4];
    #pragma unroll
    for (int mb = 0; mb < 3; ++mb)
        #pragma unroll
        for (int np = 0; np < 2; ++np)
            #pragma unroll
            for (int f = 0; f < 2; ++f)
                #pragma unroll
                for (int q = 0; q < 4; ++q) acc[mb][np][f][q] = 0.f;

    auto fill_B = [&](int buf, int gy) {
        bool rowok = (gy >= 0 && gy < HH);
        uint32_t dbase = smbB + (uint32_t)buf*DBUF*4u;
        int gys = rowok ? gy : 0;
        for (int i = tid; i < 48*134; i += 256) {
            int kp = i / 134, c2 = i - kp*134;
            int gx = c2*2 - 6;
            bool ok = rowok && gx >= 0 && gx < WW;
            const uint32_t* src = xp + kp*HWW + gys*WW + (ok ? gx : 0);
            uint32_t sz = ok ? 8u : 0u;
            asm volatile("cp.async.ca.shared.global [%0], [%1], 8, %2;"
                         :: "r"(dbase + (uint32_t)(kp*DSTR + c2*2)*4u), "l"(src), "r"(sz)
                         : "memory");
        }
    };
    auto fill_A = [&](int tap) {
        const __nv_bfloat16* src = &g_wbf[tap][0][0];
        for (int i = tid; i < 576; i += 256) {
            int row = i / 12, cu = i - row*12;
            asm volatile("cp.async.ca.shared.global [%0], [%1], 16;"
                         :: "r"(smbA + (uint32_t)(row*ASTR + cu*8)*2u),
                            "l"(src + row*C2 + cu*8) : "memory");
        }
    };
    auto stage_dky = [](int s, int& d, int& ky) {
        if (s < 9)       { d = s/3;      ky = 1; }
        else if (s < 18) { d = (s-9)/3;  ky = 0; }
        else             { d = (s-18)/3; ky = 2; }
    };

    fill_A(3);
    fill_B(0, y);
    asm volatile("cp.async.commit_group;" ::: "memory");

    #pragma unroll 1
    for (int s = 0; s < 27; ++s) {
        asm volatile("cp.async.wait_group 0;" ::: "memory");
        __syncthreads();
        if (s < 26) {
            int ns = s + 1;
            int nd, nky; stage_dky(ns, nd, nky);
            if (ns >= 9 && (ns - 9) % 3 == 0) {
                int rb = 1 + (ns - 9)/3;
                fill_B(rb & 1, y + (nky - 1)*2*(nd + 1));
                asm volatile("cp.async.commit_group;" ::: "memory");
            }
        }
        int d, ky; stage_dky(s, d, ky);
        int rb = (s < 9) ? 0 : 1 + (s - 9)/3;
        const uint32_t* bcur = Bs + (rb & 1)*DBUF;
        int dil = 2*(d + 1);
        int coloff = 6 + ((s % 3) - 1)*dil + nq*32 + (lane >> 2);
        #pragma unroll
        for (int kb = 0; kb < 6; ++kb) {
            uint32_t a[3][4];
            #pragma unroll
            for (int mb = 0; mb < 3; ++mb) {
                int row = mb*16 + (lane & 15);
                ldsm4(a[mb], smbA + (uint32_t)(row*ASTR + kb*16 + ((lane >> 4) << 3))*2u);
            }
            const uint32_t* b_lo = bcur + (kb*8 + (lane & 3))*DSTR + coloff;
            const uint32_t* b_hi = b_lo + 4*DSTR;
            #pragma unroll
            for (int np = 0; np < 2; ++np) {
                uint32_t b0 = b_lo[np*16], b1 = b_hi[np*16];
                uint32_t b2 = b_lo[np*16 + 8], b3 = b_hi[np*16 + 8];
                #pragma unroll
                for (int mb = 0; mb < 3; ++mb) {
                    mma16816(acc[mb][np][0], a[mb], b0, b1);
                    mma16816(acc[mb][np][1], a[mb], b2, b3);
                }
            }
        }
        __syncthreads();
        if (s < 26) {
            int ns = s + 1;
            int nd, nky; stage_dky(ns, nd, nky);
            fill_A(nd*9 + nky*3 + (ns % 3));
            asm volatile("cp.async.commit_group;" ::: "memory");
        }
    }
    #pragma unroll
    for (int mb = 0; mb < 3; ++mb) {
        int oc = mb*16 + (lane >> 2);
        float be0 = g_beff[oc], be1 = g_beff[oc + 8];
        #pragma unroll
        for (int np = 0; np < 2; ++np)
            #pragma unroll
            for (int f = 0; f < 2; ++f) {
                int n = nq*32 + np*16 + f*8 + (lane & 3)*2;
                *reinterpret_cast<uint32_t*>(&g_qb[b][oc][y*WW + n]) =
                    pack_bf2(acc[mb][np][f][0] + be0, acc[mb][np][f][1] + be0);
                *reinterpret_cast<uint32_t*>(&g_qb[b][oc + 8][y*WW + n]) =
                    pack_bf2(acc[mb][np][f][2] + be1, acc[mb][np][f][3] + be1);
            }
    }
}

// ---------------- QK^T dots via mma.sync + fused sumsq partials ----------------
__global__ void __launch_bounds__(256) k_dots() {
    int chunk = blockIdx.x, bh = blockIdx.y, s = blockIdx.z;
    int b = bh / NH, h = bh - b*NH;
    const uint32_t* Q = reinterpret_cast<const uint32_t*>(&g_qb[b][h*16][0]);
    const uint32_t* K = reinterpret_cast<const uint32_t*>(&g_kb[s == 0 ? 1 : 0][b][h*16][0]);
    __shared__ uint32_t Qs[16][132], Ks[16][132];
    __shared__ float redD[8][256];
    __shared__ float sqs[2][16][16];
    int tid = threadIdx.x, lane = tid & 31, w = tid >> 5;
    int c = tid >> 4, j = tid & 15;
    uint32_t smbQ = smem_u32(Qs);
    float qsq = 0.f, ksq = 0.f;
    float d0[4] = {0.f,0.f,0.f,0.f}, d1[4] = {0.f,0.f,0.f,0.f};
    int p0u = chunk*1024;
    const int rstride = HWW/2;
    for (int sub = 0; sub < 8; ++sub) {
        __syncthreads();
        int pb = p0u + sub*128;
        const uint32_t* qrow = Q + c*rstride + pb + j;
        const uint32_t* krow = K + c*rstride + pb + j;
        #pragma unroll
        for (int q = 0; q < 8; ++q) {
            uint32_t v = qrow[16*q];
            Qs[c][j + 16*q] = v;
            float lo = bf_lo(v), hi = bf_hi(v);
            qsq += lo*lo + hi*hi;
            uint32_t u = krow[16*q];
            Ks[c][j + 16*q] = u;
            lo = bf_lo(u); hi = bf_hi(u);
            ksq += lo*lo + hi*hi;
        }
        __syncthreads();
        #pragma unroll
        for (int ki = 0; ki < 2; ++ki) {
            int k0u = w*16 + ki*8;
            uint32_t a[4];
            ldsm4(a, smbQ + (uint32_t)((lane & 15)*132 + k0u + ((lane >> 4) << 2))*4u);
            uint32_t b0 = Ks[lane >> 2][k0u + (lane & 3)];
            uint32_t b1 = Ks[lane >> 2][k0u + 4 + (lane & 3)];
            uint32_t b2 = Ks[8 + (lane >> 2)][k0u + (lane & 3)];
            uint32_t b3 = Ks[8 + (lane >> 2)][k0u + 4 + (lane & 3)];
            mma16816(d0, a, b0, b1);
            mma16816(d1, a, b2, b3);
        }
    }
    {
        int cq = lane >> 2, ckb = (lane & 3)*2;
        redD[w][cq*16 + ckb]           = d0[0];
        redD[w][cq*16 + ckb + 1]       = d0[1];
        redD[w][(cq+8)*16 + ckb]       = d0[2];
        redD[w][(cq+8)*16 + ckb + 1]   = d0[3];
        redD[w][cq*16 + 8 + ckb]       = d1[0];
        redD[w][cq*16 + 8 + ckb + 1]   = d1[1];
        redD[w][(cq+8)*16 + 8 + ckb]   = d1[2];
        redD[w][(cq+8)*16 + 8 + ckb+1] = d1[3];
    }
    sqs[0][c][j] = qsq;
    sqs[1][c][j] = ksq;
    __syncthreads();
    float tot = 0.f;
    #pragma unroll
    for (int ww = 0; ww < 8; ++ww) tot += redD[ww][tid];
    int base = (((s*BB + b)*NH + h)*16 + chunk)*256;
    g_dpart[base + tid] = tot;
    if (tid < 32) {
        int set = tid >> 4, cc = tid & 15;
        float sm = 0.f;
        #pragma unroll
        for (int jj = 0; jj < 16; ++jj) sm += sqs[set][cc][jj];
        g_nsq[s][b][h][chunk][set][cc] = sm;
    }
}

// ---------------- norms + softmax + fold conv1/2 into bf16 M ----------------
__global__ void k_soft_m(const float* __restrict__ temp,
                         const float* __restrict__ w1, const float* __restrict__ w2) {
    __shared__ float As2[192][16];
    __shared__ float invs[3][2][48];
    int tid = threadIdx.x;
    for (int i = tid; i < 288; i += 256) {
        int set = i / 96, r = i - set*96;
        int b2 = r / 48, c2 = r - b2*48;
        int h2 = c2 >> 4, cc = c2 & 15;
        int ssrc = (set == 1) ? 1 : 0;
        int qk = (set == 0) ? 0 : 1;
        float sum = 0.f;
        #pragma unroll
        for (int ch2 = 0; ch2 < 16; ++ch2)
            sum += g_nsq[ssrc][b2][h2][ch2][qk][cc];
        invs[set][b2][c2] = 1.f / fmaxf(sqrtf(sum), 1e-12f);
    }
    __syncthreads();
    if (tid < 192) {
        int s = tid / 96, rem = tid - s*96;
        int b = rem / 48, rem2 = rem - b*48;
        int h = rem2 / 16, cq = rem2 - h*16;
        float v[16];
        #pragma unroll
        for (int ck = 0; ck < 16; ++ck) v[ck] = 0.f;
        int base = (((s*BB + b)*NH + h)*16)*256 + cq*16;
        for (int chunk = 0; chunk < 16; ++chunk) {
            #pragma unroll
            for (int ck = 0; ck < 16; ++ck)
                v[ck] += g_dpart[base + chunk*256 + ck];
        }
        float iq = invs[0][b][h*16 + cq];
        float tm = temp[h];
        const float* ik = (s == 0) ? &invs[2][b][h*16] : &invs[1][b][h*16];
        float mx = -1e30f;
        #pragma unroll
        for (int ck = 0; ck < 16; ++ck) { v[ck] *= iq * ik[ck] * tm; mx = fmaxf(mx, v[ck]); }
        float sum = 0.f;
        #pragma unroll
        for (int ck = 0; ck < 16; ++ck) { v[ck] = expf(v[ck] - mx); sum += v[ck]; }
        float inv = 1.f / sum;
        #pragma unroll
        for (int ck = 0; ck < 16; ++ck) As2[tid][ck] = v[ck] * inv;
    }
    __syncthreads();
    for (int idx = tid; idx < 2*BB*CC*CC; idx += blockDim.x) {
        int s = idx / (BB*CC*CC), rem = idx - s*(BB*CC*CC);
        int b = rem / (CC*CC), rem2 = rem - b*(CC*CC);
        int o = rem2 / CC, dg = rem2 - o*CC;
        int h = dg / 16, dd = dg - h*16;
        const float* wv = ((s == 0) ? w1 : w2) + o*CC + h*16;
        int arow = s*96 + b*48 + h*16;
        float acc = 0.f;
        #pragma unroll
        for (int c = 0; c < 16; ++c)
            acc += wv[c] * As2[arow + c][dd];
        g_Mbf[s*BB + b][o*CC + dg] = __float2bfloat16_rn(acc);
    }
}

// ---------------- epilogue: out = x + M @ V + bias via mma.sync ----------------
__global__ void __launch_bounds__(256) k_epilogue(const float* __restrict__ xl,
                                                  const float* __restrict__ xr,
                                                  const float* __restrict__ b1,
                                                  const float* __restrict__ b2,
                                                  float* __restrict__ out) {
    __shared__ __align__(16) __nv_bfloat16 Ms[CC*CC];
    __shared__ uint32_t Vs[24*VSTR];
    __shared__ float bss[CC];
    int p0 = blockIdx.x*256, b = blockIdx.y, s = blockIdx.z;
    int tid = threadIdx.x, lane = tid & 31, nq = tid >> 5;
    {
        const uint4* src = reinterpret_cast<const uint4*>(&g_Mbf[s*BB + b][0]);
        uint4* dst = reinterpret_cast<uint4*>(Ms);
        for (int i = tid; i < CC*CC/8; i += 256) dst[i] = src[i];
        const uint32_t* vsrc = &g_vp[s][b][0][0];
        for (int i = tid; i < 24*256; i += 256) {
            int kp = i >> 8, col = i & 255;
            Vs[kp*VSTR + col] = vsrc[kp*HWW + p0 + col];
        }
        const float* bp = s ? b2 : b1;
        for (int i = tid; i < CC; i += 256) bss[i] = bp[i];
    }
    __syncthreads();
    float acc[3][2][2][4];
    #pragma unroll
    for (int mb = 0; mb < 3; ++mb)
        #pragma unroll
        for (int np = 0; np < 2; ++np)
            #pragma unroll
            for (int f = 0; f < 2; ++f)
                #pragma unroll
                for (int q = 0; q < 4; ++q) acc[mb][np][f][q] = 0.f;
    uint32_t smbA = smem_u32(Ms);
    #pragma unroll
    for (int kb = 0; kb < 3; ++kb) {
        uint32_t a[3][4];
        #pragma unroll
        for (int mb = 0; mb < 3; ++mb) {
            int row = mb*16 + (lane & 15);
            ldsm4(a[mb], smbA + (uint32_t)(row*CC + kb*16 + ((lane >> 4) << 3))*2u);
        }
        const uint32_t* b_lo = Vs + (kb*8 + (lane & 3))*VSTR + nq*32 + (lane >> 2);
        const uint32_t* b_hi = b_lo + 4*VSTR;
        #pragma unroll
        for (int np = 0; np < 2; ++np) {
            uint32_t b0 = b_lo[np*16], b1 = b_hi[np*16];
            uint32_t b2v = b_lo[np*16 + 8], b3 = b_hi[np*16 + 8];
            #pragma unroll
            for (int mb = 0; mb < 3; ++mb) {
                mma16816(acc[mb][np][0], a[mb], b0, b1);
                mma16816(acc[mb][np][1], a[mb], b2v, b3);
            }
        }
    }
    const float* x = (s == 0 ? xl : xr) + b*CC*HWW;
    float* o = out + (s*BB + b)*CC*HWW;
    #pragma unroll
    for (int mb = 0; mb < 3; ++mb) {
        int oc0 = mb*16 + (lane >> 2), oc1 = oc0 + 8;
        float be0 = bss[oc0], be1 = bss[oc1];
        #pragma unroll
        for (int np = 0; np < 2; ++np)
            #pragma unroll
            for (int f = 0; f < 2; ++f) {
                int px = p0 + nq*32 + np*16 + f*8 + (lane & 3)*2;
                float2 x0 = *reinterpret_cast<const float2*>(&x[oc0*HWW + px]);
                float2 x1 = *reinterpret_cast<const float2*>(&x[oc1*HWW + px]);
                *reinterpret_cast<float2*>(&o[oc0*HWW + px]) =
                    make_float2(x0.x + acc[mb][np][f][0] + be0, x0.y + acc[mb][np][f][1] + be0);
                *reinterpret_cast<float2*>(&o[oc1*HWW + px]) =
                    make_float2(x1.x + acc[mb][np][f][2] + be1, x1.y + acc[mb][np][f][3] + be1);
            }
    }
}

// ---------------- launch ----------------
extern "C" void kernel_launch(void* const* d_in, const int* in_sizes, int n_in,
                              void* d_out, int out_size) {
    const float* x_l    = (const float*)d_in[0];
    const float* x_r    = (const float*)d_in[1];
    const float* ln1_w  = (const float*)d_in[2];
    const float* ln1_b  = (const float*)d_in[3];
    const float* ln2_w  = (const float*)d_in[4];
    const float* ln2_b  = (const float*)d_in[5];
    const float* qkvl_w = (const float*)d_in[6];
    const float* qkvl_b = (const float*)d_in[7];
    const float* qkvr_w = (const float*)d_in[8];
    const float* qkvr_b = (const float*)d_in[9];
    const float* dwl_w  = (const float*)d_in[10];
    const float* dwl_b  = (const float*)d_in[11];
    const float* dwr_w  = (const float*)d_in[12];
    const float* dwr_b  = (const float*)d_in[13];
    const float* dil0_w = (const float*)d_in[14];
    const float* dil0_b = (const float*)d_in[15];
    const float* dil1_w = (const float*)d_in[16];
    const float* dil1_b = (const float*)d_in[17];
    const float* dil2_w = (const float*)d_in[18];
    const float* dil2_b = (const float*)d_in[19];
    const float* convQ_w = (const float*)d_in[20];
    const float* convQ_b = (const float*)d_in[21];
    const float* conv1_w = (const float*)d_in[22];
    const float* conv1_b = (const float*)d_in[23];
    const float* conv2_w = (const float*)d_in[24];
    const float* conv2_b = (const float*)d_in[25];
    const float* temperature = (const float*)d_in[26];

    const int SMD = (2*DBUF)*4 + ATILE*2;   // 102912 + 9984 = 112896 -> 2 CTAs/SM
    cudaFuncSetAttribute(k_dilated_mma, cudaFuncAttributeMaxDynamicSharedMemorySize, SMD);

    k_misc<<<712, 256>>>(qkvl_w, qkvr_w, convQ_w, convQ_b,
                         dil0_w, dil1_w, dil2_w, dil0_b, dil1_b, dil2_b,
                         ln1_w, ln1_b, ln2_w, ln2_b, qkvl_b, qkvr_b, x_l, x_r);
    k_qkv<<<dim3(HWW/128, BB, 2), 288>>>(x_l, x_r);
    k_dw<<<dim3(HH/8, 72, 2*BB), 512>>>(dwl_w, dwl_b, dwr_w, dwr_b);
    k_dilated_mma<<<dim3(HH, BB), 256, SMD>>>();
    k_dots<<<dim3(16, BB*NH, 2), 256>>>();
    k_soft_m<<<1, 256>>>(temperature, conv1_w, conv2_w);
    k_epilogue<<<dim3(HWW/256, BB, 2), 256>>>(x_l, x_r, conv1_b, conv2_b, (float*)d_out);
}

// round 15
// speedup vs baseline: 1.0520x; 1.0520x over previous
#include <cuda_runtime.h>
#include <cuda_bf16.h>
#include <cstdint>
#include <math.h>

#define BB   2
#define CC   48
#define HH   128
#define WW   256
#define HWW  (HH*WW)          // 32768
#define C3   144
#define C2   96
#define NH   3
#define BSTR 260              // qkv B row stride (u32), 256 px tiles; 260%32==4
#define ASTR 104              // A tile row stride (bf16)
#define DSTR 268              // dilated B row stride (u32): 256 px + 12 halo; 268%32==12
#define DBUF (48*DSTR)        // u32 per dilated B buffer
#define ATILE (48*ASTR)       // bf16 per dilated A buffer
#define VSTR 260              // epilogue V row stride (u32)

// ---------------- scratch (static device globals; no allocation) ----------------
__device__ __nv_bfloat16  g_pre_bf [2][BB][C3][HWW];   // bf16 qkv after LN+1x1
__device__ __nv_bfloat16  g_kb     [2][BB][CC][HWW];   // bf16 K after dw, [c][px]
__device__ uint32_t       g_vp     [2][BB][24][HWW];   // pair-packed bf16 V after dw
__device__ uint32_t       g_xp     [BB][CC][HWW];      // channel-pair-packed bf16 [Q_l;Q_r]
__device__ __nv_bfloat16  g_qb     [BB][CC][HWW];      // bf16 fused dilated+convQ output
__device__ __nv_bfloat16  g_wbf    [27][64][C2];       // folded bf16 dilated weights
__device__ __nv_bfloat16  g_wq     [2][C3][CC];        // bf16 W' = W * diag(lnw)
__device__ float          g_S      [2*C3];             // rowsum of W'
__device__ float          g_Cb     [2*C3];             // W@lnb + bias
__device__ float          g_mu     [2][BB][HWW];
__device__ float          g_rs     [2][BB][HWW];
__device__ float          g_beff   [CC];
__device__ float          g_dpart  [2*BB*NH*16*256];
__device__ float          g_nsq    [2][BB][NH][16][2][16];
__device__ __nv_bfloat16  g_Mbf    [2*BB][CC*CC];

__device__ __forceinline__ uint32_t smem_u32(const void* p) {
    uint32_t a;
    asm("{ .reg .u64 t; cvta.to.shared.u64 t, %1; cvt.u32.u64 %0, t; }" : "=r"(a) : "l"(p));
    return a;
}
__device__ __forceinline__ void ldsm4(uint32_t* r, uint32_t addr) {
    asm volatile("ldmatrix.sync.aligned.m8n8.x4.shared.b16 {%0,%1,%2,%3}, [%4];"
        : "=r"(r[0]), "=r"(r[1]), "=r"(r[2]), "=r"(r[3]) : "r"(addr));
}
__device__ __forceinline__ void mma16816(float* c, const uint32_t* a, uint32_t b0, uint32_t b1) {
    asm volatile("mma.sync.aligned.m16n8k16.row.col.f32.bf16.bf16.f32 "
        "{%0,%1,%2,%3}, {%4,%5,%6,%7}, {%8,%9}, {%0,%1,%2,%3};"
        : "+f"(c[0]), "+f"(c[1]), "+f"(c[2]), "+f"(c[3])
        : "r"(a[0]), "r"(a[1]), "r"(a[2]), "r"(a[3]), "r"(b0), "r"(b1));
}
__device__ __forceinline__ uint32_t pack_bf2(float a, float b) {
    return (uint32_t)__bfloat16_as_ushort(__float2bfloat16_rn(a))
         | ((uint32_t)__bfloat16_as_ushort(__float2bfloat16_rn(b)) << 16);
}
__device__ __forceinline__ void st_bf2(__nv_bfloat16* p, float a, float b) {
    *reinterpret_cast<uint32_t*>(p) = pack_bf2(a, b);
}
__device__ __forceinline__ float bf_lo(uint32_t u) {
    return __bfloat162float(__ushort_as_bfloat16((unsigned short)(u & 0xFFFF)));
}
__device__ __forceinline__ float bf_hi(uint32_t u) {
    return __bfloat162float(__ushort_as_bfloat16((unsigned short)(u >> 16)));
}

// ---------------- merged prelude: W' + fold_w + fold_b + S/C + LN stats ----------------
__global__ void k_misc(const float* __restrict__ wl, const float* __restrict__ wr,
                       const float* __restrict__ cqw, const float* __restrict__ cqb,
                       const float* __restrict__ d0w, const float* __restrict__ d1w,
                       const float* __restrict__ d2w,
                       const float* __restrict__ d0b, const float* __restrict__ d1b,
                       const float* __restrict__ d2b,
                       const float* __restrict__ ln1w, const float* __restrict__ ln1b,
                       const float* __restrict__ ln2w, const float* __restrict__ ln2b,
                       const float* __restrict__ qbl, const float* __restrict__ qbr,
                       const float* __restrict__ xl, const float* __restrict__ xr) {
    int blk = blockIdx.x, tid = threadIdx.x;
    __shared__ float smf[192];
    if (blk < 54) {                               // W' = W * diag(lnw) -> bf16
        int i = blk*256 + tid;
        int s = i / (C3*CC), r = i - s*(C3*CC);
        int c = r % CC;
        const float* lw = s ? ln2w : ln1w;
        reinterpret_cast<__nv_bfloat16*>(g_wq)[i] =
            __float2bfloat16_rn((s ? wr : wl)[r] * lw[c]);
    } else if (blk < 198) {                       // fold_w: 144 blocks (o, d)
        int idx = blk - 54;
        int o = idx % CC, d = idx / CC;
        const float* dw = (d == 0) ? d0w : (d == 1) ? d1w : d2w;
        float* qr = smf;
        for (int j = tid; j < C2; j += 256)
            qr[j] = cqw[o*(3*C2) + d*C2 + j];
        __syncthreads();
        for (int ik = tid; ik < C2*9; ik += 256) {
            float acc = 0.f;
            for (int j = 0; j < C2; ++j)
                acc += qr[j] * dw[j*(C2*9) + ik];
            int i = ik / 9, kk = ik - i*9;
            g_wbf[d*9 + kk][o][i] = __float2bfloat16_rn(acc);
        }
    } else if (blk == 198) {                      // fold_b (dilated bias)
        if (tid < 192) {
            int o = tid >> 2, q = tid & 3;
            float acc = 0.f;
            for (int j = q*72; j < q*72 + 72; ++j) {
                int dd = j / 96, jj = j - dd*96;
                const float* bp = (dd == 0) ? d0b : (dd == 1) ? d1b : d2b;
                acc += cqw[o*288 + j] * bp[jj];
            }
            smf[tid] = acc;
        }
        __syncthreads();
        if (tid < CC)
            g_beff[tid] = cqb[tid] + smf[tid*4] + smf[tid*4+1] + smf[tid*4+2] + smf[tid*4+3];
    } else if (blk == 199) {                      // S/C per branch
        for (int i = tid; i < 2*C3; i += 256) {
            int s = i / C3, o = i - s*C3;
            const float* w  = s ? wr : wl;
            const float* lw = s ? ln2w : ln1w;
            const float* lb = s ? ln2b : ln1b;
            float S = 0.f, C = 0.f;
            for (int c = 0; c < CC; ++c) {
                float wv = w[o*CC + c];
                S += wv * lw[c];
                C += wv * lb[c];
            }
            g_S[i]  = S;
            g_Cb[i] = C + (s ? qbr : qbl)[o];
        }
    } else {                                      // LN stats: 512 blocks
        int blk2 = blk - 200;
        int branch = blk2 >> 8, rem = blk2 & 255;
        int b = rem >> 7, p0 = (rem & 127)*256;
        const float* x = (branch ? xr : xl) + b*CC*HWW;
        int p = p0 + tid;
        float mu = 0.f;
        #pragma unroll
        for (int c = 0; c < CC; ++c) mu += x[c*HWW + p];
        mu *= (1.f/CC);
        float var = 0.f;
        #pragma unroll
        for (int c = 0; c < CC; ++c) { float t = x[c*HWW + p] - mu; var += t*t; }
        g_mu[branch][b][p] = mu;
        g_rs[branch][b][p] = rsqrtf(var*(1.f/CC) + 1e-6f);
    }
}

// ---------------- 1x1 qkv GEMM on raw x (256-px tiles), LN folded into epilogue ----------------
__global__ void __launch_bounds__(288) k_qkv(const float* __restrict__ xl,
                                             const float* __restrict__ xr) {
    __shared__ uint32_t Bs[24*BSTR];
    __shared__ __align__(16) __nv_bfloat16 As[C3*CC];
    __shared__ float Ss[C3], Cs[C3], mus[256], rss[256];
    int p0 = blockIdx.x*256, b = blockIdx.y, branch = blockIdx.z;
    int tid = threadIdx.x, lane = tid & 31, wid = tid >> 5;
    const float* x = (branch ? xr : xl) + b*CC*HWW;
    {
        const uint4* src = reinterpret_cast<const uint4*>(&g_wq[branch][0][0]);
        uint4* dst = reinterpret_cast<uint4*>(As);
        for (int i = tid; i < C3*CC/8; i += 288) dst[i] = src[i];
        for (int i = tid; i < C3; i += 288) { Ss[i] = g_S[branch*C3 + i]; Cs[i] = g_Cb[branch*C3 + i]; }
        for (int i = tid; i < 256; i += 288) {
            mus[i] = g_mu[branch][b][p0 + i];
            rss[i] = g_rs[branch][b][p0 + i];
        }
        for (int i = tid; i < 24*256; i += 288) {
            int kp = i >> 8, p = i & 255;
            Bs[kp*BSTR + p] = pack_bf2(x[(2*kp)*HWW + p0 + p], x[(2*kp+1)*HWW + p0 + p]);
        }
    }
    __syncthreads();
    uint32_t smbA = smem_u32(As);
    int r0 = lane >> 2, cb = (lane & 3)*2;
    int oc0 = wid*16 + r0, oc1 = oc0 + 8;
    float S0 = Ss[oc0], S1 = Ss[oc1];
    float C0 = Cs[oc0], C1 = Cs[oc1];
    __nv_bfloat16* o0 = &g_pre_bf[branch][b][oc0][p0];
    __nv_bfloat16* o1 = &g_pre_bf[branch][b][oc1][p0];
    #pragma unroll
    for (int quarter = 0; quarter < 4; ++quarter) {
        float acc[4][2][4];
        #pragma unroll
        for (int np = 0; np < 4; ++np)
            #pragma unroll
            for (int f = 0; f < 2; ++f)
                #pragma unroll
                for (int q = 0; q < 4; ++q) acc[np][f][q] = 0.f;
        #pragma unroll
        for (int kb = 0; kb < 3; ++kb) {
            uint32_t a[4];
            int row = wid*16 + (lane & 15);
            ldsm4(a, smbA + (uint32_t)(row*CC + kb*16 + ((lane >> 4) << 3))*2u);
            const uint32_t* b_lo = Bs + (kb*8 + (lane & 3))*BSTR + (lane >> 2) + quarter*64;
            const uint32_t* b_hi = b_lo + 4*BSTR;
            #pragma unroll
            for (int np = 0; np < 4; ++np) {
                uint32_t b0 = b_lo[np*16], b1 = b_hi[np*16];
                uint32_t b2 = b_lo[np*16 + 8], b3 = b_hi[np*16 + 8];
                mma16816(acc[np][0], a, b0, b1);
                mma16816(acc[np][1], a, b2, b3);
            }
        }
        #pragma unroll
        for (int np = 0; np < 4; ++np)
            #pragma unroll
            for (int f = 0; f < 2; ++f) {
                int c = quarter*64 + np*16 + f*8 + cb;
                float m0 = mus[c], r0v = rss[c];
                float m1 = mus[c+1], r1v = rss[c+1];
                st_bf2(o0 + c, r0v*(acc[np][f][0] - m0*S0) + C0,
                               r1v*(acc[np][f][1] - m1*S0) + C0);
                st_bf2(o1 + c, r0v*(acc[np][f][2] - m0*S1) + C1,
                               r1v*(acc[np][f][3] - m1*S1) + C1);
            }
    }
}

// ---------------- depthwise 3x3, channel-pair blocks, 8-row tiles ----------------
__global__ void __launch_bounds__(512) k_dw(const float* __restrict__ wl, const float* __restrict__ bl,
                                            const float* __restrict__ wr, const float* __restrict__ brb) {
    int z = blockIdx.z; int branch = z >> 1, b = z & 1;
    int chp = blockIdx.y;
    int c0 = 2*chp;
    int y0 = blockIdx.x * 8;
    __shared__ __align__(16) float rows[2][10][264];
    const float* wbase = (branch == 0 ? wl : wr);
    const float* bbase = (branch == 0 ? bl : brb);
    int tid = threadIdx.x;

    for (int idx = tid; idx < 2*10*64; idx += 512) {
        int cc = idx / 640, rem = idx - cc*640;
        int r = rem >> 6, c4 = rem & 63;
        int gy = y0 - 1 + r;
        float4 f = make_float4(0.f, 0.f, 0.f, 0.f);
        if (gy >= 0 && gy < HH) {
            const __nv_bfloat16* in = &g_pre_bf[branch][b][c0 + cc][0];
            uint2 v = *reinterpret_cast<const uint2*>(&in[gy*WW + c4*4]);
            f.x = bf_lo(v.x); f.y = bf_hi(v.x);
            f.z = bf_lo(v.y); f.w = bf_hi(v.y);
        }
        *reinterpret_cast<float4*>(&rows[cc][r][4 + 4*c4]) = f;
    }
    if (tid < 20) { int cc = tid / 10, r = tid % 10; rows[cc][r][3] = 0.f; rows[cc][r][260] = 0.f; }
    __syncthreads();

    int r  = tid >> 6;
    int x0 = (tid & 63) * 4;
    float out[2][4];
    #pragma unroll
    for (int cc = 0; cc < 2; ++cc) {
        const float* w = wbase + (c0 + cc)*9;
        float bias = bbase[c0 + cc];
        float a0 = bias, a1 = bias, a2 = bias, a3 = bias;
        #pragma unroll
        for (int ky = 0; ky < 3; ++ky) {
            const float* rp = &rows[cc][r + ky][3 + x0];
            float v0 = rp[0];
            float4 vm = *reinterpret_cast<const float4*>(rp + 1);
            float v5 = rp[5];
            float w0 = w[ky*3], w1 = w[ky*3+1], w2 = w[ky*3+2];
            a0 += w0*v0   + w1*vm.x + w2*vm.y;
            a1 += w0*vm.x + w1*vm.y + w2*vm.z;
            a2 += w0*vm.y + w1*vm.z + w2*vm.w;
            a3 += w0*vm.z + w1*vm.w + w2*v5;
        }
        out[cc][0] = a0; out[cc][1] = a1; out[cc][2] = a2; out[cc][3] = a3;
    }
    int px = (y0 + r)*WW + x0;
    if (chp < 24) {
        uint4 u;
        u.x = pack_bf2(out[0][0], out[1][0]); u.y = pack_bf2(out[0][1], out[1][1]);
        u.z = pack_bf2(out[0][2], out[1][2]); u.w = pack_bf2(out[0][3], out[1][3]);
        *reinterpret_cast<uint4*>(&g_xp[b][branch*24 + chp][px]) = u;
    } else if (chp < 48) {
        int kc = c0 - CC;
        uint2 u0, u1;
        u0.x = pack_bf2(out[0][0], out[0][1]); u0.y = pack_bf2(out[0][2], out[0][3]);
        u1.x = pack_bf2(out[1][0], out[1][1]); u1.y = pack_bf2(out[1][2], out[1][3]);
        *reinterpret_cast<uint2*>(&g_kb[branch][b][kc][px])     = u0;
        *reinterpret_cast<uint2*>(&g_kb[branch][b][kc + 1][px]) = u1;
    } else {
        uint4 u;
        u.x = pack_bf2(out[0][0], out[1][0]); u.y = pack_bf2(out[0][1], out[1][1]);
        u.z = pack_bf2(out[0][2], out[1][2]); u.w = pack_bf2(out[0][3], out[1][3]);
        *reinterpret_cast<uint4*>(&g_vp[branch][b][chp - 48][px]) = u;
    }
}

// ---------------- fused dilated convs + convQ: deep B prefetch (>=3 stages cover) ----------------
// B row schedule: row rr used at stages [9+3(rr-1) .. 11+3(rr-1)] (rr>=1), row 0 at 0..8.
// Row rr buffer = rr&1, freed after stage 8+3(rr-2); fill issued right after that stage.
__global__ void __launch_bounds__(256, 2) k_dilated_mma() {
    extern __shared__ __align__(16) uint32_t smx[];
    uint32_t* Bs = smx;
    __nv_bfloat16* As = reinterpret_cast<__nv_bfloat16*>(smx + 2*DBUF);
    uint32_t smbB = smem_u32(Bs), smbA = smem_u32(As);
    int y = blockIdx.x, b = blockIdx.y;
    int tid = threadIdx.x, lane = tid & 31, nq = tid >> 5;
    const uint32_t* xp = &g_xp[b][0][0];

    float acc[3][2][2][4];
    #pragma unroll
    for (int mb = 0; mb < 3; ++mb)
        #pragma unroll
        for (int np = 0; np < 2; ++np)
            #pragma unroll
            for (int f = 0; f < 2; ++f)
                #pragma unroll
                for (int q = 0; q < 4; ++q) acc[mb][np][f][q] = 0.f;

    auto fill_B = [&](int buf, int gy) {
        bool rowok = (gy >= 0 && gy < HH);
        uint32_t dbase = smbB + (uint32_t)buf*DBUF*4u;
        int gys = rowok ? gy : 0;
        for (int i = tid; i < 48*134; i += 256) {
            int kp = i / 134, c2 = i - kp*134;
            int gx = c2*2 - 6;
            bool ok = rowok && gx >= 0 && gx < WW;
            const uint32_t* src = xp + kp*HWW + gys*WW + (ok ? gx : 0);
            uint32_t sz = ok ? 8u : 0u;
            asm volatile("cp.async.ca.shared.global [%0], [%1], 8, %2;"
                         :: "r"(dbase + (uint32_t)(kp*DSTR + c2*2)*4u), "l"(src), "r"(sz)
                         : "memory");
        }
    };
    auto fill_A = [&](int tap) {
        const __nv_bfloat16* src = &g_wbf[tap][0][0];
        for (int i = tid; i < 576; i += 256) {
            int row = i / 12, cu = i - row*12;
            asm volatile("cp.async.ca.shared.global [%0], [%1], 16;"
                         :: "r"(smbA + (uint32_t)(row*ASTR + cu*8)*2u),
                            "l"(src + row*C2 + cu*8) : "memory");
        }
    };
    auto stage_dky = [](int s, int& d, int& ky) {
        if (s < 9)       { d = s/3;      ky = 1; }
        else if (s < 18) { d = (s-9)/3;  ky = 0; }
        else             { d = (s-18)/3; ky = 2; }
    };
    auto row_gy = [&](int rr) {
        return (rr <= 3) ? (y - 2*rr) : (y + 2*(rr - 3));
    };

    // prologue: A for stage 0 (tap 3), B row 0 (buf 0), B row 1 (buf 1, used from stage 9)
    fill_A(3);
    fill_B(0, y);
    fill_B(1, row_gy(1));
    asm volatile("cp.async.commit_group;" ::: "memory");

    #pragma unroll 1
    for (int s = 0; s < 27; ++s) {
        asm volatile("cp.async.wait_group 0;" ::: "memory");
        __syncthreads();
        int d, ky; stage_dky(s, d, ky);
        int rb = (s < 9) ? 0 : 1 + (s - 9)/3;
        const uint32_t* bcur = Bs + (rb & 1)*DBUF;
        int dil = 2*(d + 1);
        int coloff = 6 + ((s % 3) - 1)*dil + nq*32 + (lane >> 2);
        #pragma unroll
        for (int kb = 0; kb < 6; ++kb) {
            uint32_t a[3][4];
            #pragma unroll
            for (int mb = 0; mb < 3; ++mb) {
                int row = mb*16 + (lane & 15);
                ldsm4(a[mb], smbA + (uint32_t)(row*ASTR + kb*16 + ((lane >> 4) << 3))*2u);
            }
            const uint32_t* b_lo = bcur + (kb*8 + (lane & 3))*DSTR + coloff;
            const uint32_t* b_hi = b_lo + 4*DSTR;
            #pragma unroll
            for (int np = 0; np < 2; ++np) {
                uint32_t b0 = b_lo[np*16], b1 = b_hi[np*16];
                uint32_t b2 = b_lo[np*16 + 8], b3 = b_hi[np*16 + 8];
                #pragma unroll
                for (int mb = 0; mb < 3; ++mb) {
                    mma16816(acc[mb][np][0], a[mb], b0, b1);
                    mma16816(acc[mb][np][1], a[mb], b2, b3);
                }
            }
        }
        __syncthreads();   // all warps done reading A (and freed B buffer if last use)
        if (s < 26) {
            int ns = s + 1;
            int nd, nky; stage_dky(ns, nd, nky);
            fill_A(nd*9 + nky*3 + (ns % 3));
            if (s >= 8 && s <= 20 && (s - 8) % 3 == 0) {   // buffer freed: prefetch row rr = (s-8)/3 + 2
                int rr = (s - 8)/3 + 2;
                fill_B(rr & 1, row_gy(rr));
            }
            asm volatile("cp.async.commit_group;" ::: "memory");
        }
    }
    #pragma unroll
    for (int mb = 0; mb < 3; ++mb) {
        int oc = mb*16 + (lane >> 2);
        float be0 = g_beff[oc], be1 = g_beff[oc + 8];
        #pragma unroll
        for (int np = 0; np < 2; ++np)
            #pragma unroll
            for (int f = 0; f < 2; ++f) {
                int n = nq*32 + np*16 + f*8 + (lane & 3)*2;
                *reinterpret_cast<uint32_t*>(&g_qb[b][oc][y*WW + n]) =
                    pack_bf2(acc[mb][np][f][0] + be0, acc[mb][np][f][1] + be0);
                *reinterpret_cast<uint32_t*>(&g_qb[b][oc + 8][y*WW + n]) =
                    pack_bf2(acc[mb][np][f][2] + be1, acc[mb][np][f][3] + be1);
            }
    }
}

// ---------------- QK^T dots via mma.sync + fused sumsq partials ----------------
__global__ void __launch_bounds__(256) k_dots() {
    int chunk = blockIdx.x, bh = blockIdx.y, s = blockIdx.z;
    int b = bh / NH, h = bh - b*NH;
    const uint32_t* Q = reinterpret_cast<const uint32_t*>(&g_qb[b][h*16][0]);
    const uint32_t* K = reinterpret_cast<const uint32_t*>(&g_kb[s == 0 ? 1 : 0][b][h*16][0]);
    __shared__ uint32_t Qs[16][132], Ks[16][132];
    __shared__ float redD[8][256];
    __shared__ float sqs[2][16][16];
    int tid = threadIdx.x, lane = tid & 31, w = tid >> 5;
    int c = tid >> 4, j = tid & 15;
    uint32_t smbQ = smem_u32(Qs);
    float qsq = 0.f, ksq = 0.f;
    float d0[4] = {0.f,0.f,0.f,0.f}, d1[4] = {0.f,0.f,0.f,0.f};
    int p0u = chunk*1024;
    const int rstride = HWW/2;
    for (int sub = 0; sub < 8; ++sub) {
        __syncthreads();
        int pb = p0u + sub*128;
        const uint32_t* qrow = Q + c*rstride + pb + j;
        const uint32_t* krow = K + c*rstride + pb + j;
        #pragma unroll
        for (int q = 0; q < 8; ++q) {
            uint32_t v = qrow[16*q];
            Qs[c][j + 16*q] = v;
            float lo = bf_lo(v), hi = bf_hi(v);
            qsq += lo*lo + hi*hi;
            uint32_t u = krow[16*q];
            Ks[c][j + 16*q] = u;
            lo = bf_lo(u); hi = bf_hi(u);
            ksq += lo*lo + hi*hi;
        }
        __syncthreads();
        #pragma unroll
        for (int ki = 0; ki < 2; ++ki) {
            int k0u = w*16 + ki*8;
            uint32_t a[4];
            ldsm4(a, smbQ + (uint32_t)((lane & 15)*132 + k0u + ((lane >> 4) << 2))*4u);
            uint32_t b0 = Ks[lane >> 2][k0u + (lane & 3)];
            uint32_t b1 = Ks[lane >> 2][k0u + 4 + (lane & 3)];
            uint32_t b2 = Ks[8 + (lane >> 2)][k0u + (lane & 3)];
            uint32_t b3 = Ks[8 + (lane >> 2)][k0u + 4 + (lane & 3)];
            mma16816(d0, a, b0, b1);
            mma16816(d1, a, b2, b3);
        }
    }
    {
        int cq = lane >> 2, ckb = (lane & 3)*2;
        redD[w][cq*16 + ckb]           = d0[0];
        redD[w][cq*16 + ckb + 1]       = d0[1];
        redD[w][(cq+8)*16 + ckb]       = d0[2];
        redD[w][(cq+8)*16 + ckb + 1]   = d0[3];
        redD[w][cq*16 + 8 + ckb]       = d1[0];
        redD[w][cq*16 + 8 + ckb + 1]   = d1[1];
        redD[w][(cq+8)*16 + 8 + ckb]   = d1[2];
        redD[w][(cq+8)*16 + 8 + ckb+1] = d1[3];
    }
    sqs[0][c][j] = qsq;
    sqs[1][c][j] = ksq;
    __syncthreads();
    float tot = 0.f;
    #pragma unroll
    for (int ww = 0; ww < 8; ++ww) tot += redD[ww][tid];
    int base = (((s*BB + b)*NH + h)*16 + chunk)*256;
    g_dpart[base + tid] = tot;
    if (tid < 32) {
        int set = tid >> 4, cc = tid & 15;
        float sm = 0.f;
        #pragma unroll
        for (int jj = 0; jj < 16; ++jj) sm += sqs[set][cc][jj];
        g_nsq[s][b][h][chunk][set][cc] = sm;
    }
}

// ---------------- norms + softmax + fold conv1/2 into bf16 M ----------------
__global__ void k_soft_m(const float* __restrict__ temp,
                         const float* __restrict__ w1, const float* __restrict__ w2) {
    __shared__ float As2[192][16];
    __shared__ float invs[3][2][48];
    int tid = threadIdx.x;
    for (int i = tid; i < 288; i += 256) {
        int set = i / 96, r = i - set*96;
        int b2 = r / 48, c2 = r - b2*48;
        int h2 = c2 >> 4, cc = c2 & 15;
        int ssrc = (set == 1) ? 1 : 0;
        int qk = (set == 0) ? 0 : 1;
        float sum = 0.f;
        #pragma unroll
        for (int ch2 = 0; ch2 < 16; ++ch2)
            sum += g_nsq[ssrc][b2][h2][ch2][qk][cc];
        invs[set][b2][c2] = 1.f / fmaxf(sqrtf(sum), 1e-12f);
    }
    __syncthreads();
    if (tid < 192) {
        int s = tid / 96, rem = tid - s*96;
        int b = rem / 48, rem2 = rem - b*48;
        int h = rem2 / 16, cq = rem2 - h*16;
        float v[16];
        #pragma unroll
        for (int ck = 0; ck < 16; ++ck) v[ck] = 0.f;
        int base = (((s*BB + b)*NH + h)*16)*256 + cq*16;
        for (int chunk = 0; chunk < 16; ++chunk) {
            #pragma unroll
            for (int ck = 0; ck < 16; ++ck)
                v[ck] += g_dpart[base + chunk*256 + ck];
        }
        float iq = invs[0][b][h*16 + cq];
        float tm = temp[h];
        const float* ik = (s == 0) ? &invs[2][b][h*16] : &invs[1][b][h*16];
        float mx = -1e30f;
        #pragma unroll
        for (int ck = 0; ck < 16; ++ck) { v[ck] *= iq * ik[ck] * tm; mx = fmaxf(mx, v[ck]); }
        float sum = 0.f;
        #pragma unroll
        for (int ck = 0; ck < 16; ++ck) { v[ck] = expf(v[ck] - mx); sum += v[ck]; }
        float inv = 1.f / sum;
        #pragma unroll
        for (int ck = 0; ck < 16; ++ck) As2[tid][ck] = v[ck] * inv;
    }
    __syncthreads();
    for (int idx = tid; idx < 2*BB*CC*CC; idx += blockDim.x) {
        int s = idx / (BB*CC*CC), rem = idx - s*(BB*CC*CC);
        int b = rem / (CC*CC), rem2 = rem - b*(CC*CC);
        int o = rem2 / CC, dg = rem2 - o*CC;
        int h = dg / 16, dd = dg - h*16;
        const float* wv = ((s == 0) ? w1 : w2) + o*CC + h*16;
        int arow = s*96 + b*48 + h*16;
        float acc = 0.f;
        #pragma unroll
        for (int c = 0; c < 16; ++c)
            acc += wv[c] * As2[arow + c][dd];
        g_Mbf[s*BB + b][o*CC + dg] = __float2bfloat16_rn(acc);
    }
}

// ---------------- epilogue: out = x + M @ V + bias via mma.sync ----------------
__global__ void __launch_bounds__(256) k_epilogue(const float* __restrict__ xl,
                                                  const float* __restrict__ xr,
                                                  const float* __restrict__ b1,
                                                  const float* __restrict__ b2,
                                                  float* __restrict__ out) {
    __shared__ __align__(16) __nv_bfloat16 Ms[CC*CC];
    __shared__ uint32_t Vs[24*VSTR];
    __shared__ float bss[CC];
    int p0 = blockIdx.x*256, b = blockIdx.y, s = blockIdx.z;
    int tid = threadIdx.x, lane = tid & 31, nq = tid >> 5;
    {
        const uint4* src = reinterpret_cast<const uint4*>(&g_Mbf[s*BB + b][0]);
        uint4* dst = reinterpret_cast<uint4*>(Ms);
        for (int i = tid; i < CC*CC/8; i += 256) dst[i] = src[i];
        const uint32_t* vsrc = &g_vp[s][b][0][0];
        for (int i = tid; i < 24*256; i += 256) {
            int kp = i >> 8, col = i & 255;
            Vs[kp*VSTR + col] = vsrc[kp*HWW + p0 + col];
        }
        const float* bp = s ? b2 : b1;
        for (int i = tid; i < CC; i += 256) bss[i] = bp[i];
    }
    __syncthreads();
    float acc[3][2][2][4];
    #pragma unroll
    for (int mb = 0; mb < 3; ++mb)
        #pragma unroll
        for (int np = 0; np < 2; ++np)
            #pragma unroll
            for (int f = 0; f < 2; ++f)
                #pragma unroll
                for (int q = 0; q < 4; ++q) acc[mb][np][f][q] = 0.f;
    uint32_t smbA = smem_u32(Ms);
    #pragma unroll
    for (int kb = 0; kb < 3; ++kb) {
        uint32_t a[3][4];
        #pragma unroll
        for (int mb = 0; mb < 3; ++mb) {
            int row = mb*16 + (lane & 15);
            ldsm4(a[mb], smbA + (uint32_t)(row*CC + kb*16 + ((lane >> 4) << 3))*2u);
        }
        const uint32_t* b_lo = Vs + (kb*8 + (lane & 3))*VSTR + nq*32 + (lane >> 2);
        const uint32_t* b_hi = b_lo + 4*VSTR;
        #pragma unroll
        for (int np = 0; np < 2; ++np) {
            uint32_t b0 = b_lo[np*16], b1 = b_hi[np*16];
            uint32_t b2v = b_lo[np*16 + 8], b3 = b_hi[np*16 + 8];
            #pragma unroll
            for (int mb = 0; mb < 3; ++mb) {
                mma16816(acc[mb][np][0], a[mb], b0, b1);
                mma16816(acc[mb][np][1], a[mb], b2v, b3);
            }
        }
    }
    const float* x = (s == 0 ? xl : xr) + b*CC*HWW;
    float* o = out + (s*BB + b)*CC*HWW;
    #pragma unroll
    for (int mb = 0; mb < 3; ++mb) {
        int oc0 = mb*16 + (lane >> 2), oc1 = oc0 + 8;
        float be0 = bss[oc0], be1 = bss[oc1];
        #pragma unroll
        for (int np = 0; np < 2; ++np)
            #pragma unroll
            for (int f = 0; f < 2; ++f) {
                int px = p0 + nq*32 + np*16 + f*8 + (lane & 3)*2;
                float2 x0 = *reinterpret_cast<const float2*>(&x[oc0*HWW + px]);
                float2 x1 = *reinterpret_cast<const float2*>(&x[oc1*HWW + px]);
                *reinterpret_cast<float2*>(&o[oc0*HWW + px]) =
                    make_float2(x0.x + acc[mb][np][f][0] + be0, x0.y + acc[mb][np][f][1] + be0);
                *reinterpret_cast<float2*>(&o[oc1*HWW + px]) =
                    make_float2(x1.x + acc[mb][np][f][2] + be1, x1.y + acc[mb][np][f][3] + be1);
            }
    }
}

// ---------------- launch ----------------
extern "C" void kernel_launch(void* const* d_in, const int* in_sizes, int n_in,
                              void* d_out, int out_size) {
    const float* x_l    = (const float*)d_in[0];
    const float* x_r    = (const float*)d_in[1];
    const float* ln1_w  = (const float*)d_in[2];
    const float* ln1_b  = (const float*)d_in[3];
    const float* ln2_w  = (const float*)d_in[4];
    const float* ln2_b  = (const float*)d_in[5];
    const float* qkvl_w = (const float*)d_in[6];
    const float* qkvl_b = (const float*)d_in[7];
    const float* qkvr_w = (const float*)d_in[8];
    const float* qkvr_b = (const float*)d_in[9];
    const float* dwl_w  = (const float*)d_in[10];
    const float* dwl_b  = (const float*)d_in[11];
    const float* dwr_w  = (const float*)d_in[12];
    const float* dwr_b  = (const float*)d_in[13];
    const float* dil0_w = (const float*)d_in[14];
    const float* dil0_b = (const float*)d_in[15];
    const float* dil1_w = (const float*)d_in[16];
    const float* dil1_b = (const float*)d_in[17];
    const float* dil2_w = (const float*)d_in[18];
    const float* dil2_b = (const float*)d_in[19];
    const float* convQ_w = (const float*)d_in[20];
    const float* convQ_b = (const float*)d_in[21];
    const float* conv1_w = (const float*)d_in[22];
    const float* conv1_b = (const float*)d_in[23];
    const float* conv2_w = (const float*)d_in[24];
    const float* conv2_b = (const float*)d_in[25];
    const float* temperature = (const float*)d_in[26];

    const int SMD = (2*DBUF)*4 + ATILE*2;   // 102912 + 9984 = 112896 -> 2 CTAs/SM
    cudaFuncSetAttribute(k_dilated_mma, cudaFuncAttributeMaxDynamicSharedMemorySize, SMD);

    k_misc<<<712, 256>>>(qkvl_w, qkvr_w, convQ_w, convQ_b,
                         dil0_w, dil1_w, dil2_w, dil0_b, dil1_b, dil2_b,
                         ln1_w, ln1_b, ln2_w, ln2_b, qkvl_b, qkvr_b, x_l, x_r);
    k_qkv<<<dim3(HWW/256, BB, 2), 288>>>(x_l, x_r);
    k_dw<<<dim3(HH/8, 72, 2*BB), 512>>>(dwl_w, dwl_b, dwr_w, dwr_b);
    k_dilated_mma<<<dim3(HH, BB), 256, SMD>>>();
    k_dots<<<dim3(16, BB*NH, 2), 256>>>();
    k_soft_m<<<1, 256>>>(temperature, conv1_w, conv2_w);
    k_epilogue<<<dim3(HWW/256, BB, 2), 256>>>(x_l, x_r, conv1_b, conv2_b, (float*)d_out);
}

// round 16
// speedup vs baseline: 1.1167x; 1.0616x over previous
#include <cuda_runtime.h>
#include <cuda_bf16.h>
#include <cstdint>
#include <math.h>

#define BB   2
#define CC   48
#define HH   128
#define WW   256
#define HWW  (HH*WW)          // 32768
#define C3   144
#define C2   96
#define NH   3
#define BSTR 260              // qkv B row stride (u32), 256 px tiles; 260%32==4
#define ASTR 104              // A tile row stride (bf16)
#define DSTR 268              // dilated B row stride (u32): 256 px + 12 halo; 268%32==12
#define DBUF (48*DSTR)        // u32 per dilated B buffer
#define ATILE (48*ASTR)       // bf16 per dilated A buffer
#define VSTR 260              // epilogue V row stride (u32)

// ---------------- scratch (static device globals; no allocation) ----------------
__device__ __nv_bfloat16  g_pre_bf [2][BB][C3][HWW];   // bf16 qkv after LN+1x1
__device__ __nv_bfloat16  g_kb     [2][BB][CC][HWW];   // bf16 K after dw, [c][px]
__device__ uint32_t       g_vp     [2][BB][24][HWW];   // pair-packed bf16 V after dw
__device__ uint32_t       g_xp     [BB][CC][HWW];      // channel-pair-packed bf16 [Q_l;Q_r]
__device__ __nv_bfloat16  g_qb     [BB][CC][HWW];      // bf16 fused dilated+convQ output
__device__ __nv_bfloat16  g_wbf    [27][64][C2];       // folded bf16 dilated weights
__device__ __nv_bfloat16  g_wq     [2][C3][CC];        // bf16 W' = W * diag(lnw)
__device__ float          g_S      [2*C3];             // rowsum of W'
__device__ float          g_Cb     [2*C3];             // W@lnb + bias
__device__ float          g_mu     [2][BB][HWW];
__device__ float          g_rs     [2][BB][HWW];
__device__ float          g_beff   [CC];
__device__ float          g_dpart  [2*BB*NH*16*256];
__device__ float          g_nsq    [2][BB][NH][16][2][16];
__device__ __nv_bfloat16  g_Mbf    [2*BB][CC*CC];

__device__ __forceinline__ uint32_t smem_u32(const void* p) {
    uint32_t a;
    asm("{ .reg .u64 t; cvta.to.shared.u64 t, %1; cvt.u32.u64 %0, t; }" : "=r"(a) : "l"(p));
    return a;
}
__device__ __forceinline__ void ldsm4(uint32_t* r, uint32_t addr) {
    asm volatile("ldmatrix.sync.aligned.m8n8.x4.shared.b16 {%0,%1,%2,%3}, [%4];"
        : "=r"(r[0]), "=r"(r[1]), "=r"(r[2]), "=r"(r[3]) : "r"(addr));
}
__device__ __forceinline__ void mma16816(float* c, const uint32_t* a, uint32_t b0, uint32_t b1) {
    asm volatile("mma.sync.aligned.m16n8k16.row.col.f32.bf16.bf16.f32 "
        "{%0,%1,%2,%3}, {%4,%5,%6,%7}, {%8,%9}, {%0,%1,%2,%3};"
        : "+f"(c[0]), "+f"(c[1]), "+f"(c[2]), "+f"(c[3])
        : "r"(a[0]), "r"(a[1]), "r"(a[2]), "r"(a[3]), "r"(b0), "r"(b1));
}
__device__ __forceinline__ uint32_t pack_bf2(float a, float b) {
    return (uint32_t)__bfloat16_as_ushort(__float2bfloat16_rn(a))
         | ((uint32_t)__bfloat16_as_ushort(__float2bfloat16_rn(b)) << 16);
}
__device__ __forceinline__ void st_bf2(__nv_bfloat16* p, float a, float b) {
    *reinterpret_cast<uint32_t*>(p) = pack_bf2(a, b);
}
__device__ __forceinline__ float bf_lo(uint32_t u) {
    return __bfloat162float(__ushort_as_bfloat16((unsigned short)(u & 0xFFFF)));
}
__device__ __forceinline__ float bf_hi(uint32_t u) {
    return __bfloat162float(__ushort_as_bfloat16((unsigned short)(u >> 16)));
}

// ---------------- merged prelude: W' + fold_w + fold_b + S/C + LN stats (single pass) ----------------
__global__ void k_misc(const float* __restrict__ wl, const float* __restrict__ wr,
                       const float* __restrict__ cqw, const float* __restrict__ cqb,
                       const float* __restrict__ d0w, const float* __restrict__ d1w,
                       const float* __restrict__ d2w,
                       const float* __restrict__ d0b, const float* __restrict__ d1b,
                       const float* __restrict__ d2b,
                       const float* __restrict__ ln1w, const float* __restrict__ ln1b,
                       const float* __restrict__ ln2w, const float* __restrict__ ln2b,
                       const float* __restrict__ qbl, const float* __restrict__ qbr,
                       const float* __restrict__ xl, const float* __restrict__ xr) {
    int blk = blockIdx.x, tid = threadIdx.x;
    __shared__ float smf[192];
    if (blk < 54) {                               // W' = W * diag(lnw) -> bf16
        int i = blk*256 + tid;
        int s = i / (C3*CC), r = i - s*(C3*CC);
        int c = r % CC;
        const float* lw = s ? ln2w : ln1w;
        reinterpret_cast<__nv_bfloat16*>(g_wq)[i] =
            __float2bfloat16_rn((s ? wr : wl)[r] * lw[c]);
    } else if (blk < 198) {                       // fold_w: 144 blocks (o, d)
        int idx = blk - 54;
        int o = idx % CC, d = idx / CC;
        const float* dw = (d == 0) ? d0w : (d == 1) ? d1w : d2w;
        float* qr = smf;
        for (int j = tid; j < C2; j += 256)
            qr[j] = cqw[o*(3*C2) + d*C2 + j];
        __syncthreads();
        for (int ik = tid; ik < C2*9; ik += 256) {
            float acc = 0.f;
            for (int j = 0; j < C2; ++j)
                acc += qr[j] * dw[j*(C2*9) + ik];
            int i = ik / 9, kk = ik - i*9;
            g_wbf[d*9 + kk][o][i] = __float2bfloat16_rn(acc);
        }
    } else if (blk == 198) {                      // fold_b (dilated bias)
        if (tid < 192) {
            int o = tid >> 2, q = tid & 3;
            float acc = 0.f;
            for (int j = q*72; j < q*72 + 72; ++j) {
                int dd = j / 96, jj = j - dd*96;
                const float* bp = (dd == 0) ? d0b : (dd == 1) ? d1b : d2b;
                acc += cqw[o*288 + j] * bp[jj];
            }
            smf[tid] = acc;
        }
        __syncthreads();
        if (tid < CC)
            g_beff[tid] = cqb[tid] + smf[tid*4] + smf[tid*4+1] + smf[tid*4+2] + smf[tid*4+3];
    } else if (blk == 199) {                      // S/C per branch
        for (int i = tid; i < 2*C3; i += 256) {
            int s = i / C3, o = i - s*C3;
            const float* w  = s ? wr : wl;
            const float* lw = s ? ln2w : ln1w;
            const float* lb = s ? ln2b : ln1b;
            float S = 0.f, C = 0.f;
            for (int c = 0; c < CC; ++c) {
                float wv = w[o*CC + c];
                S += wv * lw[c];
                C += wv * lb[c];
            }
            g_S[i]  = S;
            g_Cb[i] = C + (s ? qbr : qbl)[o];
        }
    } else {                                      // LN stats (single pass): 512 blocks
        int blk2 = blk - 200;
        int branch = blk2 >> 8, rem = blk2 & 255;
        int b = rem >> 7, p0 = (rem & 127)*256;
        const float* x = (branch ? xr : xl) + b*CC*HWW;
        int p = p0 + tid;
        float sum = 0.f, ssq = 0.f;
        #pragma unroll
        for (int c = 0; c < CC; ++c) {
            float v = x[c*HWW + p];
            sum += v;
            ssq += v*v;
        }
        float mu = sum * (1.f/CC);
        float var = fmaxf(ssq * (1.f/CC) - mu*mu, 0.f);
        g_mu[branch][b][p] = mu;
        g_rs[branch][b][p] = rsqrtf(var + 1e-6f);
    }
}

// ---------------- 1x1 qkv GEMM on raw x (256-px tiles), LN folded into epilogue ----------------
__global__ void __launch_bounds__(288) k_qkv(const float* __restrict__ xl,
                                             const float* __restrict__ xr) {
    __shared__ uint32_t Bs[24*BSTR];
    __shared__ __align__(16) __nv_bfloat16 As[C3*CC];
    __shared__ float Ss[C3], Cs[C3], mus[256], rss[256];
    int p0 = blockIdx.x*256, b = blockIdx.y, branch = blockIdx.z;
    int tid = threadIdx.x, lane = tid & 31, wid = tid >> 5;
    const float* x = (branch ? xr : xl) + b*CC*HWW;
    {
        const uint4* src = reinterpret_cast<const uint4*>(&g_wq[branch][0][0]);
        uint4* dst = reinterpret_cast<uint4*>(As);
        for (int i = tid; i < C3*CC/8; i += 288) dst[i] = src[i];
        for (int i = tid; i < C3; i += 288) { Ss[i] = g_S[branch*C3 + i]; Cs[i] = g_Cb[branch*C3 + i]; }
        for (int i = tid; i < 256; i += 288) {
            mus[i] = g_mu[branch][b][p0 + i];
            rss[i] = g_rs[branch][b][p0 + i];
        }
        for (int i = tid; i < 24*256; i += 288) {
            int kp = i >> 8, p = i & 255;
            Bs[kp*BSTR + p] = pack_bf2(x[(2*kp)*HWW + p0 + p], x[(2*kp+1)*HWW + p0 + p]);
        }
    }
    __syncthreads();
    uint32_t smbA = smem_u32(As);
    int r0 = lane >> 2, cb = (lane & 3)*2;
    int oc0 = wid*16 + r0, oc1 = oc0 + 8;
    float S0 = Ss[oc0], S1 = Ss[oc1];
    float C0 = Cs[oc0], C1 = Cs[oc1];
    __nv_bfloat16* o0 = &g_pre_bf[branch][b][oc0][p0];
    __nv_bfloat16* o1 = &g_pre_bf[branch][b][oc1][p0];
    #pragma unroll
    for (int quarter = 0; quarter < 4; ++quarter) {
        float acc[4][2][4];
        #pragma unroll
        for (int np = 0; np < 4; ++np)
            #pragma unroll
            for (int f = 0; f < 2; ++f)
                #pragma unroll
                for (int q = 0; q < 4; ++q) acc[np][f][q] = 0.f;
        #pragma unroll
        for (int kb = 0; kb < 3; ++kb) {
            uint32_t a[4];
            int row = wid*16 + (lane & 15);
            ldsm4(a, smbA + (uint32_t)(row*CC + kb*16 + ((lane >> 4) << 3))*2u);
            const uint32_t* b_lo = Bs + (kb*8 + (lane & 3))*BSTR + (lane >> 2) + quarter*64;
            const uint32_t* b_hi = b_lo + 4*BSTR;
            #pragma unroll
            for (int np = 0; np < 4; ++np) {
                uint32_t b0 = b_lo[np*16], b1 = b_hi[np*16];
                uint32_t b2 = b_lo[np*16 + 8], b3 = b_hi[np*16 + 8];
                mma16816(acc[np][0], a, b0, b1);
                mma16816(acc[np][1], a, b2, b3);
            }
        }
        #pragma unroll
        for (int np = 0; np < 4; ++np)
            #pragma unroll
            for (int f = 0; f < 2; ++f) {
                int c = quarter*64 + np*16 + f*8 + cb;
                float m0 = mus[c], r0v = rss[c];
                float m1 = mus[c+1], r1v = rss[c+1];
                st_bf2(o0 + c, r0v*(acc[np][f][0] - m0*S0) + C0,
                               r1v*(acc[np][f][1] - m1*S0) + C0);
                st_bf2(o1 + c, r0v*(acc[np][f][2] - m0*S1) + C1,
                               r1v*(acc[np][f][3] - m1*S1) + C1);
            }
    }
}

// ---------------- depthwise 3x3, channel-pair blocks, 8-row tiles ----------------
__global__ void __launch_bounds__(512) k_dw(const float* __restrict__ wl, const float* __restrict__ bl,
                                            const float* __restrict__ wr, const float* __restrict__ brb) {
    int z = blockIdx.z; int branch = z >> 1, b = z & 1;
    int chp = blockIdx.y;
    int c0 = 2*chp;
    int y0 = blockIdx.x * 8;
    __shared__ __align__(16) float rows[2][10][264];
    const float* wbase = (branch == 0 ? wl : wr);
    const float* bbase = (branch == 0 ? bl : brb);
    int tid = threadIdx.x;

    for (int idx = tid; idx < 2*10*64; idx += 512) {
        int cc = idx / 640, rem = idx - cc*640;
        int r = rem >> 6, c4 = rem & 63;
        int gy = y0 - 1 + r;
        float4 f = make_float4(0.f, 0.f, 0.f, 0.f);
        if (gy >= 0 && gy < HH) {
            const __nv_bfloat16* in = &g_pre_bf[branch][b][c0 + cc][0];
            uint2 v = *reinterpret_cast<const uint2*>(&in[gy*WW + c4*4]);
            f.x = bf_lo(v.x); f.y = bf_hi(v.x);
            f.z = bf_lo(v.y); f.w = bf_hi(v.y);
        }
        *reinterpret_cast<float4*>(&rows[cc][r][4 + 4*c4]) = f;
    }
    if (tid < 20) { int cc = tid / 10, r = tid % 10; rows[cc][r][3] = 0.f; rows[cc][r][260] = 0.f; }
    __syncthreads();

    int r  = tid >> 6;
    int x0 = (tid & 63) * 4;
    float out[2][4];
    #pragma unroll
    for (int cc = 0; cc < 2; ++cc) {
        const float* w = wbase + (c0 + cc)*9;
        float bias = bbase[c0 + cc];
        float a0 = bias, a1 = bias, a2 = bias, a3 = bias;
        #pragma unroll
        for (int ky = 0; ky < 3; ++ky) {
            const float* rp = &rows[cc][r + ky][3 + x0];
            float v0 = rp[0];
            float4 vm = *reinterpret_cast<const float4*>(rp + 1);
            float v5 = rp[5];
            float w0 = w[ky*3], w1 = w[ky*3+1], w2 = w[ky*3+2];
            a0 += w0*v0   + w1*vm.x + w2*vm.y;
            a1 += w0*vm.x + w1*vm.y + w2*vm.z;
            a2 += w0*vm.y + w1*vm.z + w2*vm.w;
            a3 += w0*vm.z + w1*vm.w + w2*v5;
        }
        out[cc][0] = a0; out[cc][1] = a1; out[cc][2] = a2; out[cc][3] = a3;
    }
    int px = (y0 + r)*WW + x0;
    if (chp < 24) {
        uint4 u;
        u.x = pack_bf2(out[0][0], out[1][0]); u.y = pack_bf2(out[0][1], out[1][1]);
        u.z = pack_bf2(out[0][2], out[1][2]); u.w = pack_bf2(out[0][3], out[1][3]);
        *reinterpret_cast<uint4*>(&g_xp[b][branch*24 + chp][px]) = u;
    } else if (chp < 48) {
        int kc = c0 - CC;
        uint2 u0, u1;
        u0.x = pack_bf2(out[0][0], out[0][1]); u0.y = pack_bf2(out[0][2], out[0][3]);
        u1.x = pack_bf2(out[1][0], out[1][1]); u1.y = pack_bf2(out[1][2], out[1][3]);
        *reinterpret_cast<uint2*>(&g_kb[branch][b][kc][px])     = u0;
        *reinterpret_cast<uint2*>(&g_kb[branch][b][kc + 1][px]) = u1;
    } else {
        uint4 u;
        u.x = pack_bf2(out[0][0], out[1][0]); u.y = pack_bf2(out[0][1], out[1][1]);
        u.z = pack_bf2(out[0][2], out[1][2]); u.w = pack_bf2(out[0][3], out[1][3]);
        *reinterpret_cast<uint4*>(&g_vp[branch][b][chp - 48][px]) = u;
    }
}

// ---------------- fused dilated convs + convQ: deep B prefetch ----------------
__global__ void __launch_bounds__(256, 2) k_dilated_mma() {
    extern __shared__ __align__(16) uint32_t smx[];
    uint32_t* Bs = smx;
    __nv_bfloat16* As = reinterpret_cast<__nv_bfloat16*>(smx + 2*DBUF);
    uint32_t smbB = smem_u32(Bs), smbA = smem_u32(As);
    int y = blockIdx.x, b = blockIdx.y;
    int tid = threadIdx.x, lane = tid & 31, nq = tid >> 5;
    const uint32_t* xp = &g_xp[b][0][0];

    float acc[3][2][2][4];
    #pragma unroll
    for (int mb = 0; mb < 3; ++mb)
        #pragma unroll
        for (int np = 0; np < 2; ++np)
            #pragma unroll
            for (int f = 0; f < 2; ++f)
                #pragma unroll
                for (int q = 0; q < 4; ++q) acc[mb][np][f][q] = 0.f;

    auto fill_B = [&](int buf, int gy) {
        bool rowok = (gy >= 0 && gy < HH);
        uint32_t dbase = smbB + (uint32_t)buf*DBUF*4u;
        int gys = rowok ? gy : 0;
        for (int i = tid; i < 48*134; i += 256) {
            int kp = i / 134, c2 = i - kp*134;
            int gx = c2*2 - 6;
            bool ok = rowok && gx >= 0 && gx < WW;
            const uint32_t* src = xp + kp*HWW + gys*WW + (ok ? gx : 0);
            uint32_t sz = ok ? 8u : 0u;
            asm volatile("cp.async.ca.shared.global [%0], [%1], 8, %2;"
                         :: "r"(dbase + (uint32_t)(kp*DSTR + c2*2)*4u), "l"(src), "r"(sz)
                         : "memory");
        }
    };
    auto fill_A = [&](int tap) {
        const __nv_bfloat16* src = &g_wbf[tap][0][0];
        for (int i = tid; i < 576; i += 256) {
            int row = i / 12, cu = i - row*12;
            asm volatile("cp.async.ca.shared.global [%0], [%1], 16;"
                         :: "r"(smbA + (uint32_t)(row*ASTR + cu*8)*2u),
                            "l"(src + row*C2 + cu*8) : "memory");
        }
    };
    auto stage_dky = [](int s, int& d, int& ky) {
        if (s < 9)       { d = s/3;      ky = 1; }
        else if (s < 18) { d = (s-9)/3;  ky = 0; }
        else             { d = (s-18)/3; ky = 2; }
    };
    auto row_gy = [&](int rr) {
        return (rr <= 3) ? (y - 2*rr) : (y + 2*(rr - 3));
    };

    fill_A(3);
    fill_B(0, y);
    fill_B(1, row_gy(1));
    asm volatile("cp.async.commit_group;" ::: "memory");

    #pragma unroll 1
    for (int s = 0; s < 27; ++s) {
        asm volatile("cp.async.wait_group 0;" ::: "memory");
        __syncthreads();
        int d, ky; stage_dky(s, d, ky);
        int rb = (s < 9) ? 0 : 1 + (s - 9)/3;
        const uint32_t* bcur = Bs + (rb & 1)*DBUF;
        int dil = 2*(d + 1);
        int coloff = 6 + ((s % 3) - 1)*dil + nq*32 + (lane >> 2);
        #pragma unroll
        for (int kb = 0; kb < 6; ++kb) {
            uint32_t a[3][4];
            #pragma unroll
            for (int mb = 0; mb < 3; ++mb) {
                int row = mb*16 + (lane & 15);
                ldsm4(a[mb], smbA + (uint32_t)(row*ASTR + kb*16 + ((lane >> 4) << 3))*2u);
            }
            const uint32_t* b_lo = bcur + (kb*8 + (lane & 3))*DSTR + coloff;
            const uint32_t* b_hi = b_lo + 4*DSTR;
            #pragma unroll
            for (int np = 0; np < 2; ++np) {
                uint32_t b0 = b_lo[np*16], b1 = b_hi[np*16];
                uint32_t b2 = b_lo[np*16 + 8], b3 = b_hi[np*16 + 8];
                #pragma unroll
                for (int mb = 0; mb < 3; ++mb) {
                    mma16816(acc[mb][np][0], a[mb], b0, b1);
                    mma16816(acc[mb][np][1], a[mb], b2, b3);
                }
            }
        }
        __syncthreads();
        if (s < 26) {
            int ns = s + 1;
            int nd, nky; stage_dky(ns, nd, nky);
            fill_A(nd*9 + nky*3 + (ns % 3));
            if (s >= 8 && s <= 20 && (s - 8) % 3 == 0) {
                int rr = (s - 8)/3 + 2;
                fill_B(rr & 1, row_gy(rr));
            }
            asm volatile("cp.async.commit_group;" ::: "memory");
        }
    }
    #pragma unroll
    for (int mb = 0; mb < 3; ++mb) {
        int oc = mb*16 + (lane >> 2);
        float be0 = g_beff[oc], be1 = g_beff[oc + 8];
        #pragma unroll
        for (int np = 0; np < 2; ++np)
            #pragma unroll
            for (int f = 0; f < 2; ++f) {
                int n = nq*32 + np*16 + f*8 + (lane & 3)*2;
                *reinterpret_cast<uint32_t*>(&g_qb[b][oc][y*WW + n]) =
                    pack_bf2(acc[mb][np][f][0] + be0, acc[mb][np][f][1] + be0);
                *reinterpret_cast<uint32_t*>(&g_qb[b][oc + 8][y*WW + n]) =
                    pack_bf2(acc[mb][np][f][2] + be1, acc[mb][np][f][3] + be1);
            }
    }
}

// ---------------- QK^T dots via mma.sync + fused sumsq partials ----------------
__global__ void __launch_bounds__(256) k_dots() {
    int chunk = blockIdx.x, bh = blockIdx.y, s = blockIdx.z;
    int b = bh / NH, h = bh - b*NH;
    const uint32_t* Q = reinterpret_cast<const uint32_t*>(&g_qb[b][h*16][0]);
    const uint32_t* K = reinterpret_cast<const uint32_t*>(&g_kb[s == 0 ? 1 : 0][b][h*16][0]);
    __shared__ uint32_t Qs[16][132], Ks[16][132];
    __shared__ float redD[8][256];
    __shared__ float sqs[2][16][16];
    int tid = threadIdx.x, lane = tid & 31, w = tid >> 5;
    int c = tid >> 4, j = tid & 15;
    uint32_t smbQ = smem_u32(Qs);
    float qsq = 0.f, ksq = 0.f;
    float d0[4] = {0.f,0.f,0.f,0.f}, d1[4] = {0.f,0.f,0.f,0.f};
    int p0u = chunk*1024;
    const int rstride = HWW/2;
    for (int sub = 0; sub < 8; ++sub) {
        __syncthreads();
        int pb = p0u + sub*128;
        const uint32_t* qrow = Q + c*rstride + pb + j;
        const uint32_t* krow = K + c*rstride + pb + j;
        #pragma unroll
        for (int q = 0; q < 8; ++q) {
            uint32_t v = qrow[16*q];
            Qs[c][j + 16*q] = v;
            float lo = bf_lo(v), hi = bf_hi(v);
            qsq += lo*lo + hi*hi;
            uint32_t u = krow[16*q];
            Ks[c][j + 16*q] = u;
            lo = bf_lo(u); hi = bf_hi(u);
            ksq += lo*lo + hi*hi;
        }
        __syncthreads();
        #pragma unroll
        for (int ki = 0; ki < 2; ++ki) {
            int k0u = w*16 + ki*8;
            uint32_t a[4];
            ldsm4(a, smbQ + (uint32_t)((lane & 15)*132 + k0u + ((lane >> 4) << 2))*4u);
            uint32_t b0 = Ks[lane >> 2][k0u + (lane & 3)];
            uint32_t b1 = Ks[lane >> 2][k0u + 4 + (lane & 3)];
            uint32_t b2 = Ks[8 + (lane >> 2)][k0u + (lane & 3)];
            uint32_t b3 = Ks[8 + (lane >> 2)][k0u + 4 + (lane & 3)];
            mma16816(d0, a, b0, b1);
            mma16816(d1, a, b2, b3);
        }
    }
    {
        int cq = lane >> 2, ckb = (lane & 3)*2;
        redD[w][cq*16 + ckb]           = d0[0];
        redD[w][cq*16 + ckb + 1]       = d0[1];
        redD[w][(cq+8)*16 + ckb]       = d0[2];
        redD[w][(cq+8)*16 + ckb + 1]   = d0[3];
        redD[w][cq*16 + 8 + ckb]       = d1[0];
        redD[w][cq*16 + 8 + ckb + 1]   = d1[1];
        redD[w][(cq+8)*16 + 8 + ckb]   = d1[2];
        redD[w][(cq+8)*16 + 8 + ckb+1] = d1[3];
    }
    sqs[0][c][j] = qsq;
    sqs[1][c][j] = ksq;
    __syncthreads();
    float tot = 0.f;
    #pragma unroll
    for (int ww = 0; ww < 8; ++ww) tot += redD[ww][tid];
    int base = (((s*BB + b)*NH + h)*16 + chunk)*256;
    g_dpart[base + tid] = tot;
    if (tid < 32) {
        int set = tid >> 4, cc = tid & 15;
        float sm = 0.f;
        #pragma unroll
        for (int jj = 0; jj < 16; ++jj) sm += sqs[set][cc][jj];
        g_nsq[s][b][h][chunk][set][cc] = sm;
    }
}

// ---------------- norms + softmax + M-fold, parallel over (s,b) ----------------
__global__ void k_soft_m(const float* __restrict__ temp,
                         const float* __restrict__ w1, const float* __restrict__ w2) {
    int s = blockIdx.x >> 1, b = blockIdx.x & 1;
    __shared__ float As2[48][16];
    __shared__ float invq[48], invk[48];
    int tid = threadIdx.x;
    if (tid < 96) {
        int set = tid / 48, c2 = tid - set*48;
        int h2 = c2 >> 4, cc = c2 & 15;
        float sum = 0.f;
        #pragma unroll
        for (int ch2 = 0; ch2 < 16; ++ch2)
            sum += g_nsq[s][b][h2][ch2][set][cc];
        float inv = 1.f / fmaxf(sqrtf(sum), 1e-12f);
        if (set == 0) invq[c2] = inv; else invk[c2] = inv;
    }
    __syncthreads();
    if (tid < 48) {
        int h = tid >> 4;
        float v[16];
        #pragma unroll
        for (int ck = 0; ck < 16; ++ck) v[ck] = 0.f;
        int base = (((s*BB + b)*NH + h)*16)*256 + (tid & 15)*16;
        for (int chunk = 0; chunk < 16; ++chunk) {
            #pragma unroll
            for (int ck = 0; ck < 16; ++ck)
                v[ck] += g_dpart[base + chunk*256 + ck];
        }
        float iq = invq[tid];
        float tm = temp[h];
        float mx = -1e30f;
        #pragma unroll
        for (int ck = 0; ck < 16; ++ck) { v[ck] *= iq * invk[h*16 + ck] * tm; mx = fmaxf(mx, v[ck]); }
        float sum = 0.f;
        #pragma unroll
        for (int ck = 0; ck < 16; ++ck) { v[ck] = expf(v[ck] - mx); sum += v[ck]; }
        float inv = 1.f / sum;
        #pragma unroll
        for (int ck = 0; ck < 16; ++ck) As2[tid][ck] = v[ck] * inv;
    }
    __syncthreads();
    const float* wsrc = (s == 0) ? w1 : w2;
    for (int idx = tid; idx < CC*CC; idx += blockDim.x) {
        int o = idx / CC, dg = idx - o*CC;
        int h = dg >> 4, dd = dg & 15;
        const float* wv = wsrc + o*CC + h*16;
        float acc = 0.f;
        #pragma unroll
        for (int c = 0; c < 16; ++c)
            acc += wv[c] * As2[h*16 + c][dd];
        g_Mbf[s*BB + b][idx] = __float2bfloat16_rn(acc);
    }
}

// ---------------- epilogue: out = x + M @ V + bias via mma.sync ----------------
__global__ void __launch_bounds__(256) k_epilogue(const float* __restrict__ xl,
                                                  const float* __restrict__ xr,
                                                  const float* __restrict__ b1,
                                                  const float* __restrict__ b2,
                                                  float* __restrict__ out) {
    __shared__ __align__(16) __nv_bfloat16 Ms[CC*CC];
    __shared__ uint32_t Vs[24*VSTR];
    __shared__ float bss[CC];
    int p0 = blockIdx.x*256, b = blockIdx.y, s = blockIdx.z;
    int tid = threadIdx.x, lane = tid & 31, nq = tid >> 5;
    {
        const uint4* src = reinterpret_cast<const uint4*>(&g_Mbf[s*BB + b][0]);
        uint4* dst = reinterpret_cast<uint4*>(Ms);
        for (int i = tid; i < CC*CC/8; i += 256) dst[i] = src[i];
        const uint32_t* vsrc = &g_vp[s][b][0][0];
        for (int i = tid; i < 24*256; i += 256) {
            int kp = i >> 8, col = i & 255;
            Vs[kp*VSTR + col] = vsrc[kp*HWW + p0 + col];
        }
        const float* bp = s ? b2 : b1;
        for (int i = tid; i < CC; i += 256) bss[i] = bp[i];
    }
    __syncthreads();
    float acc[3][2][2][4];
    #pragma unroll
    for (int mb = 0; mb < 3; ++mb)
        #pragma unroll
        for (int np = 0; np < 2; ++np)
            #pragma unroll
            for (int f = 0; f < 2; ++f)
                #pragma unroll
                for (int q = 0; q < 4; ++q) acc[mb][np][f][q] = 0.f;
    uint32_t smbA = smem_u32(Ms);
    #pragma unroll
    for (int kb = 0; kb < 3; ++kb) {
        uint32_t a[3][4];
        #pragma unroll
        for (int mb = 0; mb < 3; ++mb) {
            int row = mb*16 + (lane & 15);
            ldsm4(a[mb], smbA + (uint32_t)(row*CC + kb*16 + ((lane >> 4) << 3))*2u);
        }
        const uint32_t* b_lo = Vs + (kb*8 + (lane & 3))*VSTR + nq*32 + (lane >> 2);
        const uint32_t* b_hi = b_lo + 4*VSTR;
        #pragma unroll
        for (int np = 0; np < 2; ++np) {
            uint32_t b0 = b_lo[np*16], b1 = b_hi[np*16];
            uint32_t b2v = b_lo[np*16 + 8], b3 = b_hi[np*16 + 8];
            #pragma unroll
            for (int mb = 0; mb < 3; ++mb) {
                mma16816(acc[mb][np][0], a[mb], b0, b1);
                mma16816(acc[mb][np][1], a[mb], b2v, b3);
            }
        }
    }
    const float* x = (s == 0 ? xl : xr) + b*CC*HWW;
    float* o = out + (s*BB + b)*CC*HWW;
    #pragma unroll
    for (int mb = 0; mb < 3; ++mb) {
        int oc0 = mb*16 + (lane >> 2), oc1 = oc0 + 8;
        float be0 = bss[oc0], be1 = bss[oc1];
        #pragma unroll
        for (int np = 0; np < 2; ++np)
            #pragma unroll
            for (int f = 0; f < 2; ++f) {
                int px = p0 + nq*32 + np*16 + f*8 + (lane & 3)*2;
                float2 x0 = *reinterpret_cast<const float2*>(&x[oc0*HWW + px]);
                float2 x1 = *reinterpret_cast<const float2*>(&x[oc1*HWW + px]);
                *reinterpret_cast<float2*>(&o[oc0*HWW + px]) =
                    make_float2(x0.x + acc[mb][np][f][0] + be0, x0.y + acc[mb][np][f][1] + be0);
                *reinterpret_cast<float2*>(&o[oc1*HWW + px]) =
                    make_float2(x1.x + acc[mb][np][f][2] + be1, x1.y + acc[mb][np][f][3] + be1);
            }
    }
}

// ---------------- launch ----------------
extern "C" void kernel_launch(void* const* d_in, const int* in_sizes, int n_in,
                              void* d_out, int out_size) {
    const float* x_l    = (const float*)d_in[0];
    const float* x_r    = (const float*)d_in[1];
    const float* ln1_w  = (const float*)d_in[2];
    const float* ln1_b  = (const float*)d_in[3];
    const float* ln2_w  = (const float*)d_in[4];
    const float* ln2_b  = (const float*)d_in[5];
    const float* qkvl_w = (const float*)d_in[6];
    const float* qkvl_b = (const float*)d_in[7];
    const float* qkvr_w = (const float*)d_in[8];
    const float* qkvr_b = (const float*)d_in[9];
    const float* dwl_w  = (const float*)d_in[10];
    const float* dwl_b  = (const float*)d_in[11];
    const float* dwr_w  = (const float*)d_in[12];
    const float* dwr_b  = (const float*)d_in[13];
    const float* dil0_w = (const float*)d_in[14];
    const float* dil0_b = (const float*)d_in[15];
    const float* dil1_w = (const float*)d_in[16];
    const float* dil1_b = (const float*)d_in[17];
    const float* dil2_w = (const float*)d_in[18];
    const float* dil2_b = (const float*)d_in[19];
    const float* convQ_w = (const float*)d_in[20];
    const float* convQ_b = (const float*)d_in[21];
    const float* conv1_w = (const float*)d_in[22];
    const float* conv1_b = (const float*)d_in[23];
    const float* conv2_w = (const float*)d_in[24];
    const float* conv2_b = (const float*)d_in[25];
    const float* temperature = (const float*)d_in[26];

    const int SMD = (2*DBUF)*4 + ATILE*2;   // 102912 + 9984 = 112896 -> 2 CTAs/SM
    cudaFuncSetAttribute(k_dilated_mma, cudaFuncAttributeMaxDynamicSharedMemorySize, SMD);

    k_misc<<<712, 256>>>(qkvl_w, qkvr_w, convQ_w, convQ_b,
                         dil0_w, dil1_w, dil2_w, dil0_b, dil1_b, dil2_b,
                         ln1_w, ln1_b, ln2_w, ln2_b, qkvl_b, qkvr_b, x_l, x_r);
    k_qkv<<<dim3(HWW/256, BB, 2), 288>>>(x_l, x_r);
    k_dw<<<dim3(HH/8, 72, 2*BB), 512>>>(dwl_w, dwl_b, dwr_w, dwr_b);
    k_dilated_mma<<<dim3(HH, BB), 256, SMD>>>();
    k_dots<<<dim3(16, BB*NH, 2), 256>>>();
    k_soft_m<<<4, 256>>>(temperature, conv1_w, conv2_w);
    k_epilogue<<<dim3(HWW/256, BB, 2), 256>>>(x_l, x_r, conv1_b, conv2_b, (float*)d_out);
}

// round 17
// speedup vs baseline: 1.1235x; 1.0061x over previous
#include <cuda_runtime.h>
#include <cuda_bf16.h>
#include <cstdint>
#include <math.h>

#define BB   2
#define CC   48
#define HH   128
#define WW   256
#define HWW  (HH*WW)          // 32768
#define C3   144
#define C2   96
#define NH   3
#define BSTR 260              // qkv B row stride (u32), 256 px tiles; 260%32==4
#define ASTR 104              // A tile row stride (bf16)
#define DSTR 268              // dilated B row stride (u32): 256 px + 12 halo; 268%32==12
#define DBUF (48*DSTR)        // u32 per dilated B buffer
#define ATILE (48*ASTR)       // bf16 per dilated A buffer
#define VSTR 260              // epilogue V row stride (u32)

// ---------------- scratch (static device globals; no allocation) ----------------
__device__ __nv_bfloat16  g_pre_bf [2][BB][C3][HWW];   // bf16 qkv after LN+1x1
__device__ __nv_bfloat16  g_kb     [2][BB][CC][HWW];   // bf16 K after dw, [c][px]
__device__ uint32_t       g_vp     [2][BB][24][HWW];   // pair-packed bf16 V after dw
__device__ uint32_t       g_xp     [BB][CC][HWW];      // channel-pair-packed bf16 [Q_l;Q_r]
__device__ __nv_bfloat16  g_qb     [BB][CC][HWW];      // bf16 fused dilated+convQ output
__device__ __nv_bfloat16  g_wbf    [27][64][C2];       // folded bf16 dilated weights
__device__ __nv_bfloat16  g_wq     [2][C3][CC];        // bf16 W' = W * diag(lnw)
__device__ float          g_S      [2*C3];             // rowsum of W'
__device__ float          g_Cb     [2*C3];             // W@lnb + bias
__device__ float          g_beff   [CC];
__device__ float          g_dpart  [2*BB*NH*16*256];
__device__ float          g_nsq    [2][BB][NH][16][2][16];
__device__ __nv_bfloat16  g_Mbf    [2*BB][CC*CC];

__device__ __forceinline__ uint32_t smem_u32(const void* p) {
    uint32_t a;
    asm("{ .reg .u64 t; cvta.to.shared.u64 t, %1; cvt.u32.u64 %0, t; }" : "=r"(a) : "l"(p));
    return a;
}
__device__ __forceinline__ void ldsm4(uint32_t* r, uint32_t addr) {
    asm volatile("ldmatrix.sync.aligned.m8n8.x4.shared.b16 {%0,%1,%2,%3}, [%4];"
        : "=r"(r[0]), "=r"(r[1]), "=r"(r[2]), "=r"(r[3]) : "r"(addr));
}
__device__ __forceinline__ void mma16816(float* c, const uint32_t* a, uint32_t b0, uint32_t b1) {
    asm volatile("mma.sync.aligned.m16n8k16.row.col.f32.bf16.bf16.f32 "
        "{%0,%1,%2,%3}, {%4,%5,%6,%7}, {%8,%9}, {%0,%1,%2,%3};"
        : "+f"(c[0]), "+f"(c[1]), "+f"(c[2]), "+f"(c[3])
        : "r"(a[0]), "r"(a[1]), "r"(a[2]), "r"(a[3]), "r"(b0), "r"(b1));
}
__device__ __forceinline__ uint32_t pack_bf2(float a, float b) {
    return (uint32_t)__bfloat16_as_ushort(__float2bfloat16_rn(a))
         | ((uint32_t)__bfloat16_as_ushort(__float2bfloat16_rn(b)) << 16);
}
__device__ __forceinline__ void st_bf2(__nv_bfloat16* p, float a, float b) {
    *reinterpret_cast<uint32_t*>(p) = pack_bf2(a, b);
}
__device__ __forceinline__ float bf_lo(uint32_t u) {
    return __bfloat162float(__ushort_as_bfloat16((unsigned short)(u & 0xFFFF)));
}
__device__ __forceinline__ float bf_hi(uint32_t u) {
    return __bfloat162float(__ushort_as_bfloat16((unsigned short)(u >> 16)));
}

// ---------------- merged prelude: W' + fold_w + fold_b + S/C ----------------
__global__ void k_misc(const float* __restrict__ wl, const float* __restrict__ wr,
                       const float* __restrict__ cqw, const float* __restrict__ cqb,
                       const float* __restrict__ d0w, const float* __restrict__ d1w,
                       const float* __restrict__ d2w,
                       const float* __restrict__ d0b, const float* __restrict__ d1b,
                       const float* __restrict__ d2b,
                       const float* __restrict__ ln1w, const float* __restrict__ ln1b,
                       const float* __restrict__ ln2w, const float* __restrict__ ln2b,
                       const float* __restrict__ qbl, const float* __restrict__ qbr) {
    int blk = blockIdx.x, tid = threadIdx.x;
    __shared__ float smf[192];
    if (blk < 54) {                               // W' = W * diag(lnw) -> bf16
        int i = blk*256 + tid;
        int s = i / (C3*CC), r = i - s*(C3*CC);
        int c = r % CC;
        const float* lw = s ? ln2w : ln1w;
        reinterpret_cast<__nv_bfloat16*>(g_wq)[i] =
            __float2bfloat16_rn((s ? wr : wl)[r] * lw[c]);
    } else if (blk < 198) {                       // fold_w: 144 blocks (o, d)
        int idx = blk - 54;
        int o = idx % CC, d = idx / CC;
        const float* dw = (d == 0) ? d0w : (d == 1) ? d1w : d2w;
        float* qr = smf;
        for (int j = tid; j < C2; j += 256)
            qr[j] = cqw[o*(3*C2) + d*C2 + j];
        __syncthreads();
        for (int ik = tid; ik < C2*9; ik += 256) {
            float acc = 0.f;
            for (int j = 0; j < C2; ++j)
                acc += qr[j] * dw[j*(C2*9) + ik];
            int i = ik / 9, kk = ik - i*9;
            g_wbf[d*9 + kk][o][i] = __float2bfloat16_rn(acc);
        }
    } else if (blk == 198) {                      // fold_b (dilated bias)
        if (tid < 192) {
            int o = tid >> 2, q = tid & 3;
            float acc = 0.f;
            for (int j = q*72; j < q*72 + 72; ++j) {
                int dd = j / 96, jj = j - dd*96;
                const float* bp = (dd == 0) ? d0b : (dd == 1) ? d1b : d2b;
                acc += cqw[o*288 + j] * bp[jj];
            }
            smf[tid] = acc;
        }
        __syncthreads();
        if (tid < CC)
            g_beff[tid] = cqb[tid] + smf[tid*4] + smf[tid*4+1] + smf[tid*4+2] + smf[tid*4+3];
    } else {                                      // S/C per branch
        for (int i = tid; i < 2*C3; i += 256) {
            int s = i / C3, o = i - s*C3;
            const float* w  = s ? wr : wl;
            const float* lw = s ? ln2w : ln1w;
            const float* lb = s ? ln2b : ln1b;
            float S = 0.f, C = 0.f;
            for (int c = 0; c < CC; ++c) {
                float wv = w[o*CC + c];
                S += wv * lw[c];
                C += wv * lb[c];
            }
            g_S[i]  = S;
            g_Cb[i] = C + (s ? qbr : qbl)[o];
        }
    }
}

// ---------------- 1x1 qkv GEMM on raw x, fused LN stats, LN in epilogue ----------------
__global__ void __launch_bounds__(288) k_qkv(const float* __restrict__ xl,
                                             const float* __restrict__ xr) {
    __shared__ uint32_t Bs[24*BSTR];
    __shared__ __align__(16) __nv_bfloat16 As[C3*CC];
    __shared__ float Ss[C3], Cs[C3], mus[256], rss[256];
    int p0 = blockIdx.x*256, b = blockIdx.y, branch = blockIdx.z;
    int tid = threadIdx.x, lane = tid & 31, wid = tid >> 5;
    const float* x = (branch ? xr : xl) + b*CC*HWW;
    {
        const uint4* src = reinterpret_cast<const uint4*>(&g_wq[branch][0][0]);
        uint4* dst = reinterpret_cast<uint4*>(As);
        for (int i = tid; i < C3*CC/8; i += 288) dst[i] = src[i];
        for (int i = tid; i < C3; i += 288) { Ss[i] = g_S[branch*C3 + i]; Cs[i] = g_Cb[branch*C3 + i]; }
        if (tid < 256) {                    // stats + B fill, one pixel column per thread
            const float* xc = x + p0 + tid;
            float sum = 0.f, ssq = 0.f;
            #pragma unroll
            for (int kp = 0; kp < 24; ++kp) {
                float v0 = xc[(2*kp)*HWW];
                float v1 = xc[(2*kp+1)*HWW];
                sum += v0 + v1;
                ssq += v0*v0 + v1*v1;
                Bs[kp*BSTR + tid] = pack_bf2(v0, v1);
            }
            float mu = sum * (1.f/CC);
            float var = fmaxf(ssq * (1.f/CC) - mu*mu, 0.f);
            mus[tid] = mu;
            rss[tid] = rsqrtf(var + 1e-6f);
        }
    }
    __syncthreads();
    uint32_t smbA = smem_u32(As);
    int r0 = lane >> 2, cb = (lane & 3)*2;
    int oc0 = wid*16 + r0, oc1 = oc0 + 8;
    float S0 = Ss[oc0], S1 = Ss[oc1];
    float C0 = Cs[oc0], C1 = Cs[oc1];
    __nv_bfloat16* o0 = &g_pre_bf[branch][b][oc0][p0];
    __nv_bfloat16* o1 = &g_pre_bf[branch][b][oc1][p0];
    #pragma unroll
    for (int quarter = 0; quarter < 4; ++quarter) {
        float acc[4][2][4];
        #pragma unroll
        for (int np = 0; np < 4; ++np)
            #pragma unroll
            for (int f = 0; f < 2; ++f)
                #pragma unroll
                for (int q = 0; q < 4; ++q) acc[np][f][q] = 0.f;
        #pragma unroll
        for (int kb = 0; kb < 3; ++kb) {
            uint32_t a[4];
            int row = wid*16 + (lane & 15);
            ldsm4(a, smbA + (uint32_t)(row*CC + kb*16 + ((lane >> 4) << 3))*2u);
            const uint32_t* b_lo = Bs + (kb*8 + (lane & 3))*BSTR + (lane >> 2) + quarter*64;
            const uint32_t* b_hi = b_lo + 4*BSTR;
            #pragma unroll
            for (int np = 0; np < 4; ++np) {
                uint32_t b0 = b_lo[np*16], b1 = b_hi[np*16];
                uint32_t b2 = b_lo[np*16 + 8], b3 = b_hi[np*16 + 8];
                mma16816(acc[np][0], a, b0, b1);
                mma16816(acc[np][1], a, b2, b3);
            }
        }
        #pragma unroll
        for (int np = 0; np < 4; ++np)
            #pragma unroll
            for (int f = 0; f < 2; ++f) {
                int c = quarter*64 + np*16 + f*8 + cb;
                float m0 = mus[c], r0v = rss[c];
                float m1 = mus[c+1], r1v = rss[c+1];
                st_bf2(o0 + c, r0v*(acc[np][f][0] - m0*S0) + C0,
                               r1v*(acc[np][f][1] - m1*S0) + C0);
                st_bf2(o1 + c, r0v*(acc[np][f][2] - m0*S1) + C1,
                               r1v*(acc[np][f][3] - m1*S1) + C1);
            }
    }
}

// ---------------- depthwise 3x3, channel-pair blocks, 8-row tiles ----------------
__global__ void __launch_bounds__(512) k_dw(const float* __restrict__ wl, const float* __restrict__ bl,
                                            const float* __restrict__ wr, const float* __restrict__ brb) {
    int z = blockIdx.z; int branch = z >> 1, b = z & 1;
    int chp = blockIdx.y;
    int c0 = 2*chp;
    int y0 = blockIdx.x * 8;
    __shared__ __align__(16) float rows[2][10][264];
    const float* wbase = (branch == 0 ? wl : wr);
    const float* bbase = (branch == 0 ? bl : brb);
    int tid = threadIdx.x;

    for (int idx = tid; idx < 2*10*64; idx += 512) {
        int cc = idx / 640, rem = idx - cc*640;
        int r = rem >> 6, c4 = rem & 63;
        int gy = y0 - 1 + r;
        float4 f = make_float4(0.f, 0.f, 0.f, 0.f);
        if (gy >= 0 && gy < HH) {
            const __nv_bfloat16* in = &g_pre_bf[branch][b][c0 + cc][0];
            uint2 v = *reinterpret_cast<const uint2*>(&in[gy*WW + c4*4]);
            f.x = bf_lo(v.x); f.y = bf_hi(v.x);
            f.z = bf_lo(v.y); f.w = bf_hi(v.y);
        }
        *reinterpret_cast<float4*>(&rows[cc][r][4 + 4*c4]) = f;
    }
    if (tid < 20) { int cc = tid / 10, r = tid % 10; rows[cc][r][3] = 0.f; rows[cc][r][260] = 0.f; }
    __syncthreads();

    int r  = tid >> 6;
    int x0 = (tid & 63) * 4;
    float out[2][4];
    #pragma unroll
    for (int cc = 0; cc < 2; ++cc) {
        const float* w = wbase + (c0 + cc)*9;
        float bias = bbase[c0 + cc];
        float a0 = bias, a1 = bias, a2 = bias, a3 = bias;
        #pragma unroll
        for (int ky = 0; ky < 3; ++ky) {
            const float* rp = &rows[cc][r + ky][3 + x0];
            float v0 = rp[0];
            float4 vm = *reinterpret_cast<const float4*>(rp + 1);
            float v5 = rp[5];
            float w0 = w[ky*3], w1 = w[ky*3+1], w2 = w[ky*3+2];
            a0 += w0*v0   + w1*vm.x + w2*vm.y;
            a1 += w0*vm.x + w1*vm.y + w2*vm.z;
            a2 += w0*vm.y + w1*vm.z + w2*vm.w;
            a3 += w0*vm.z + w1*vm.w + w2*v5;
        }
        out[cc][0] = a0; out[cc][1] = a1; out[cc][2] = a2; out[cc][3] = a3;
    }
    int px = (y0 + r)*WW + x0;
    if (chp < 24) {
        uint4 u;
        u.x = pack_bf2(out[0][0], out[1][0]); u.y = pack_bf2(out[0][1], out[1][1]);
        u.z = pack_bf2(out[0][2], out[1][2]); u.w = pack_bf2(out[0][3], out[1][3]);
        *reinterpret_cast<uint4*>(&g_xp[b][branch*24 + chp][px]) = u;
    } else if (chp < 48) {
        int kc = c0 - CC;
        uint2 u0, u1;
        u0.x = pack_bf2(out[0][0], out[0][1]); u0.y = pack_bf2(out[0][2], out[0][3]);
        u1.x = pack_bf2(out[1][0], out[1][1]); u1.y = pack_bf2(out[1][2], out[1][3]);
        *reinterpret_cast<uint2*>(&g_kb[branch][b][kc][px])     = u0;
        *reinterpret_cast<uint2*>(&g_kb[branch][b][kc + 1][px]) = u1;
    } else {
        uint4 u;
        u.x = pack_bf2(out[0][0], out[1][0]); u.y = pack_bf2(out[0][1], out[1][1]);
        u.z = pack_bf2(out[0][2], out[1][2]); u.w = pack_bf2(out[0][3], out[1][3]);
        *reinterpret_cast<uint4*>(&g_vp[branch][b][chp - 48][px]) = u;
    }
}

// ---------------- fused dilated convs + convQ: deep B prefetch ----------------
__global__ void __launch_bounds__(256, 2) k_dilated_mma() {
    extern __shared__ __align__(16) uint32_t smx[];
    uint32_t* Bs = smx;
    __nv_bfloat16* As = reinterpret_cast<__nv_bfloat16*>(smx + 2*DBUF);
    uint32_t smbB = smem_u32(Bs), smbA = smem_u32(As);
    int y = blockIdx.x, b = blockIdx.y;
    int tid = threadIdx.x, lane = tid & 31, nq = tid >> 5;
    const uint32_t* xp = &g_xp[b][0][0];

    float acc[3][2][2][4];
    #pragma unroll
    for (int mb = 0; mb < 3; ++mb)
        #pragma unroll
        for (int np = 0; np < 2; ++np)
            #pragma unroll
            for (int f = 0; f < 2; ++f)
                #pragma unroll
                for (int q = 0; q < 4; ++q) acc[mb][np][f][q] = 0.f;

    auto fill_B = [&](int buf, int gy) {
        bool rowok = (gy >= 0 && gy < HH);
        uint32_t dbase = smbB + (uint32_t)buf*DBUF*4u;
        int gys = rowok ? gy : 0;
        for (int i = tid; i < 48*134; i += 256) {
            int kp = i / 134, c2 = i - kp*134;
            int gx = c2*2 - 6;
            bool ok = rowok && gx >= 0 && gx < WW;
            const uint32_t* src = xp + kp*HWW + gys*WW + (ok ? gx : 0);
            uint32_t sz = ok ? 8u : 0u;
            asm volatile("cp.async.ca.shared.global [%0], [%1], 8, %2;"
                         :: "r"(dbase + (uint32_t)(kp*DSTR + c2*2)*4u), "l"(src), "r"(sz)
                         : "memory");
        }
    };
    auto fill_A = [&](int tap) {
        const __nv_bfloat16* src = &g_wbf[tap][0][0];
        for (int i = tid; i < 576; i += 256) {
            int row = i / 12, cu = i - row*12;
            asm volatile("cp.async.ca.shared.global [%0], [%1], 16;"
                         :: "r"(smbA + (uint32_t)(row*ASTR + cu*8)*2u),
                            "l"(src + row*C2 + cu*8) : "memory");
        }
    };
    auto stage_dky = [](int s, int& d, int& ky) {
        if (s < 9)       { d = s/3;      ky = 1; }
        else if (s < 18) { d = (s-9)/3;  ky = 0; }
        else             { d = (s-18)/3; ky = 2; }
    };
    auto row_gy = [&](int rr) {
        return (rr <= 3) ? (y - 2*rr) : (y + 2*(rr - 3));
    };

    fill_A(3);
    fill_B(0, y);
    fill_B(1, row_gy(1));
    asm volatile("cp.async.commit_group;" ::: "memory");

    #pragma unroll 1
    for (int s = 0; s < 27; ++s) {
        asm volatile("cp.async.wait_group 0;" ::: "memory");
        __syncthreads();
        int d, ky; stage_dky(s, d, ky);
        int rb = (s < 9) ? 0 : 1 + (s - 9)/3;
        const uint32_t* bcur = Bs + (rb & 1)*DBUF;
        int dil = 2*(d + 1);
        int coloff = 6 + ((s % 3) - 1)*dil + nq*32 + (lane >> 2);
        #pragma unroll
        for (int kb = 0; kb < 6; ++kb) {
            uint32_t a[3][4];
            #pragma unroll
            for (int mb = 0; mb < 3; ++mb) {
                int row = mb*16 + (lane & 15);
                ldsm4(a[mb], smbA + (uint32_t)(row*ASTR + kb*16 + ((lane >> 4) << 3))*2u);
            }
            const uint32_t* b_lo = bcur + (kb*8 + (lane & 3))*DSTR + coloff;
            const uint32_t* b_hi = b_lo + 4*DSTR;
            #pragma unroll
            for (int np = 0; np < 2; ++np) {
                uint32_t b0 = b_lo[np*16], b1 = b_hi[np*16];
                uint32_t b2 = b_lo[np*16 + 8], b3 = b_hi[np*16 + 8];
                #pragma unroll
                for (int mb = 0; mb < 3; ++mb) {
                    mma16816(acc[mb][np][0], a[mb], b0, b1);
                    mma16816(acc[mb][np][1], a[mb], b2, b3);
                }
            }
        }
        __syncthreads();
        if (s < 26) {
            int ns = s + 1;
            int nd, nky; stage_dky(ns, nd, nky);
            fill_A(nd*9 + nky*3 + (ns % 3));
            if (s >= 8 && s <= 20 && (s - 8) % 3 == 0) {
                int rr = (s - 8)/3 + 2;
                fill_B(rr & 1, row_gy(rr));
            }
            asm volatile("cp.async.commit_group;" ::: "memory");
        }
    }
    #pragma unroll
    for (int mb = 0; mb < 3; ++mb) {
        int oc = mb*16 + (lane >> 2);
        float be0 = g_beff[oc], be1 = g_beff[oc + 8];
        #pragma unroll
        for (int np = 0; np < 2; ++np)
            #pragma unroll
            for (int f = 0; f < 2; ++f) {
                int n = nq*32 + np*16 + f*8 + (lane & 3)*2;
                *reinterpret_cast<uint32_t*>(&g_qb[b][oc][y*WW + n]) =
                    pack_bf2(acc[mb][np][f][0] + be0, acc[mb][np][f][1] + be0);
                *reinterpret_cast<uint32_t*>(&g_qb[b][oc + 8][y*WW + n]) =
                    pack_bf2(acc[mb][np][f][2] + be1, acc[mb][np][f][3] + be1);
            }
    }
}

// ---------------- QK^T dots via mma.sync + fused sumsq partials ----------------
__global__ void __launch_bounds__(256) k_dots() {
    int chunk = blockIdx.x, bh = blockIdx.y, s = blockIdx.z;
    int b = bh / NH, h = bh - b*NH;
    const uint32_t* Q = reinterpret_cast<const uint32_t*>(&g_qb[b][h*16][0]);
    const uint32_t* K = reinterpret_cast<const uint32_t*>(&g_kb[s == 0 ? 1 : 0][b][h*16][0]);
    __shared__ uint32_t Qs[16][132], Ks[16][132];
    __shared__ float redD[8][256];
    __shared__ float sqs[2][16][16];
    int tid = threadIdx.x, lane = tid & 31, w = tid >> 5;
    int c = tid >> 4, j = tid & 15;
    uint32_t smbQ = smem_u32(Qs);
    float qsq = 0.f, ksq = 0.f;
    float d0[4] = {0.f,0.f,0.f,0.f}, d1[4] = {0.f,0.f,0.f,0.f};
    int p0u = chunk*1024;
    const int rstride = HWW/2;
    for (int sub = 0; sub < 8; ++sub) {
        __syncthreads();
        int pb = p0u + sub*128;
        const uint32_t* qrow = Q + c*rstride + pb + j;
        const uint32_t* krow = K + c*rstride + pb + j;
        #pragma unroll
        for (int q = 0; q < 8; ++q) {
            uint32_t v = qrow[16*q];
            Qs[c][j + 16*q] = v;
            float lo = bf_lo(v), hi = bf_hi(v);
            qsq += lo*lo + hi*hi;
            uint32_t u = krow[16*q];
            Ks[c][j + 16*q] = u;
            lo = bf_lo(u); hi = bf_hi(u);
            ksq += lo*lo + hi*hi;
        }
        __syncthreads();
        #pragma unroll
        for (int ki = 0; ki < 2; ++ki) {
            int k0u = w*16 + ki*8;
            uint32_t a[4];
            ldsm4(a, smbQ + (uint32_t)((lane & 15)*132 + k0u + ((lane >> 4) << 2))*4u);
            uint32_t b0 = Ks[lane >> 2][k0u + (lane & 3)];
            uint32_t b1 = Ks[lane >> 2][k0u + 4 + (lane & 3)];
            uint32_t b2 = Ks[8 + (lane >> 2)][k0u + (lane & 3)];
            uint32_t b3 = Ks[8 + (lane >> 2)][k0u + 4 + (lane & 3)];
            mma16816(d0, a, b0, b1);
            mma16816(d1, a, b2, b3);
        }
    }
    {
        int cq = lane >> 2, ckb = (lane & 3)*2;
        redD[w][cq*16 + ckb]           = d0[0];
        redD[w][cq*16 + ckb + 1]       = d0[1];
        redD[w][(cq+8)*16 + ckb]       = d0[2];
        redD[w][(cq+8)*16 + ckb + 1]   = d0[3];
        redD[w][cq*16 + 8 + ckb]       = d1[0];
        redD[w][cq*16 + 8 + ckb + 1]   = d1[1];
        redD[w][(cq+8)*16 + 8 + ckb]   = d1[2];
        redD[w][(cq+8)*16 + 8 + ckb+1] = d1[3];
    }
    sqs[0][c][j] = qsq;
    sqs[1][c][j] = ksq;
    __syncthreads();
    float tot = 0.f;
    #pragma unroll
    for (int ww = 0; ww < 8; ++ww) tot += redD[ww][tid];
    int base = (((s*BB + b)*NH + h)*16 + chunk)*256;
    g_dpart[base + tid] = tot;
    if (tid < 32) {
        int set = tid >> 4, cc = tid & 15;
        float sm = 0.f;
        #pragma unroll
        for (int jj = 0; jj < 16; ++jj) sm += sqs[set][cc][jj];
        g_nsq[s][b][h][chunk][set][cc] = sm;
    }
}

// ---------------- norms + softmax + M-fold, parallel over (s,b) ----------------
__global__ void k_soft_m(const float* __restrict__ temp,
                         const float* __restrict__ w1, const float* __restrict__ w2) {
    int s = blockIdx.x >> 1, b = blockIdx.x & 1;
    __shared__ float As2[48][16];
    __shared__ float invq[48], invk[48];
    int tid = threadIdx.x;
    if (tid < 96) {
        int set = tid / 48, c2 = tid - set*48;
        int h2 = c2 >> 4, cc = c2 & 15;
        float sum = 0.f;
        #pragma unroll
        for (int ch2 = 0; ch2 < 16; ++ch2)
            sum += g_nsq[s][b][h2][ch2][set][cc];
        float inv = 1.f / fmaxf(sqrtf(sum), 1e-12f);
        if (set == 0) invq[c2] = inv; else invk[c2] = inv;
    }
    __syncthreads();
    if (tid < 48) {
        int h = tid >> 4;
        float v[16];
        #pragma unroll
        for (int ck = 0; ck < 16; ++ck) v[ck] = 0.f;
        int base = (((s*BB + b)*NH + h)*16)*256 + (tid & 15)*16;
        for (int chunk = 0; chunk < 16; ++chunk) {
            #pragma unroll
            for (int ck = 0; ck < 16; ++ck)
                v[ck] += g_dpart[base + chunk*256 + ck];
        }
        float iq = invq[tid];
        float tm = temp[h];
        float mx = -1e30f;
        #pragma unroll
        for (int ck = 0; ck < 16; ++ck) { v[ck] *= iq * invk[h*16 + ck] * tm; mx = fmaxf(mx, v[ck]); }
        float sum = 0.f;
        #pragma unroll
        for (int ck = 0; ck < 16; ++ck) { v[ck] = expf(v[ck] - mx); sum += v[ck]; }
        float inv = 1.f / sum;
        #pragma unroll
        for (int ck = 0; ck < 16; ++ck) As2[tid][ck] = v[ck] * inv;
    }
    __syncthreads();
    const float* wsrc = (s == 0) ? w1 : w2;
    for (int idx = tid; idx < CC*CC; idx += blockDim.x) {
        int o = idx / CC, dg = idx - o*CC;
        int h = dg >> 4, dd = dg & 15;
        const float* wv = wsrc + o*CC + h*16;
        float acc = 0.f;
        #pragma unroll
        for (int c = 0; c < 16; ++c)
            acc += wv[c] * As2[h*16 + c][dd];
        g_Mbf[s*BB + b][idx] = __float2bfloat16_rn(acc);
    }
}

// ---------------- epilogue: out = x + M @ V + bias via mma.sync ----------------
__global__ void __launch_bounds__(256) k_epilogue(const float* __restrict__ xl,
                                                  const float* __restrict__ xr,
                                                  const float* __restrict__ b1,
                                                  const float* __restrict__ b2,
                                                  float* __restrict__ out) {
    __shared__ __align__(16) __nv_bfloat16 Ms[CC*CC];
    __shared__ uint32_t Vs[24*VSTR];
    __shared__ float bss[CC];
    int p0 = blockIdx.x*256, b = blockIdx.y, s = blockIdx.z;
    int tid = threadIdx.x, lane = tid & 31, nq = tid >> 5;
    {
        const uint4* src = reinterpret_cast<const uint4*>(&g_Mbf[s*BB + b][0]);
        uint4* dst = reinterpret_cast<uint4*>(Ms);
        for (int i = tid; i < CC*CC/8; i += 256) dst[i] = src[i];
        const uint32_t* vsrc = &g_vp[s][b][0][0];
        for (int i = tid; i < 24*256; i += 256) {
            int kp = i >> 8, col = i & 255;
            Vs[kp*VSTR + col] = vsrc[kp*HWW + p0 + col];
        }
        const float* bp = s ? b2 : b1;
        for (int i = tid; i < CC; i += 256) bss[i] = bp[i];
    }
    __syncthreads();
    float acc[3][2][2][4];
    #pragma unroll
    for (int mb = 0; mb < 3; ++mb)
        #pragma unroll
        for (int np = 0; np < 2; ++np)
            #pragma unroll
            for (int f = 0; f < 2; ++f)
                #pragma unroll
                for (int q = 0; q < 4; ++q) acc[mb][np][f][q] = 0.f;
    uint32_t smbA = smem_u32(Ms);
    #pragma unroll
    for (int kb = 0; kb < 3; ++kb) {
        uint32_t a[3][4];
        #pragma unroll
        for (int mb = 0; mb < 3; ++mb) {
            int row = mb*16 + (lane & 15);
            ldsm4(a[mb], smbA + (uint32_t)(row*CC + kb*16 + ((lane >> 4) << 3))*2u);
        }
        const uint32_t* b_lo = Vs + (kb*8 + (lane & 3))*VSTR + nq*32 + (lane >> 2);
        const uint32_t* b_hi = b_lo + 4*VSTR;
        #pragma unroll
        for (int np = 0; np < 2; ++np) {
            uint32_t b0 = b_lo[np*16], b1 = b_hi[np*16];
            uint32_t b2v = b_lo[np*16 + 8], b3 = b_hi[np*16 + 8];
            #pragma unroll
            for (int mb = 0; mb < 3; ++mb) {
                mma16816(acc[mb][np][0], a[mb], b0, b1);
                mma16816(acc[mb][np][1], a[mb], b2v, b3);
            }
        }
    }
    const float* x = (s == 0 ? xl : xr) + b*CC*HWW;
    float* o = out + (s*BB + b)*CC*HWW;
    #pragma unroll
    for (int mb = 0; mb < 3; ++mb) {
        int oc0 = mb*16 + (lane >> 2), oc1 = oc0 + 8;
        float be0 = bss[oc0], be1 = bss[oc1];
        #pragma unroll
        for (int np = 0; np < 2; ++np)
            #pragma unroll
            for (int f = 0; f < 2; ++f) {
                int px = p0 + nq*32 + np*16 + f*8 + (lane & 3)*2;
                float2 x0 = *reinterpret_cast<const float2*>(&x[oc0*HWW + px]);
                float2 x1 = *reinterpret_cast<const float2*>(&x[oc1*HWW + px]);
                *reinterpret_cast<float2*>(&o[oc0*HWW + px]) =
                    make_float2(x0.x + acc[mb][np][f][0] + be0, x0.y + acc[mb][np][f][1] + be0);
                *reinterpret_cast<float2*>(&o[oc1*HWW + px]) =
                    make_float2(x1.x + acc[mb][np][f][2] + be1, x1.y + acc[mb][np][f][3] + be1);
            }
    }
}

// ---------------- launch ----------------
extern "C" void kernel_launch(void* const* d_in, const int* in_sizes, int n_in,
                              void* d_out, int out_size) {
    const float* x_l    = (const float*)d_in[0];
    const float* x_r    = (const float*)d_in[1];
    const float* ln1_w  = (const float*)d_in[2];
    const float* ln1_b  = (const float*)d_in[3];
    const float* ln2_w  = (const float*)d_in[4];
    const float* ln2_b  = (const float*)d_in[5];
    const float* qkvl_w = (const float*)d_in[6];
    const float* qkvl_b = (const float*)d_in[7];
    const float* qkvr_w = (const float*)d_in[8];
    const float* qkvr_b = (const float*)d_in[9];
    const float* dwl_w  = (const float*)d_in[10];
    const float* dwl_b  = (const float*)d_in[11];
    const float* dwr_w  = (const float*)d_in[12];
    const float* dwr_b  = (const float*)d_in[13];
    const float* dil0_w = (const float*)d_in[14];
    const float* dil0_b = (const float*)d_in[15];
    const float* dil1_w = (const float*)d_in[16];
    const float* dil1_b = (const float*)d_in[17];
    const float* dil2_w = (const float*)d_in[18];
    const float* dil2_b = (const float*)d_in[19];
    const float* convQ_w = (const float*)d_in[20];
    const float* convQ_b = (const float*)d_in[21];
    const float* conv1_w = (const float*)d_in[22];
    const float* conv1_b = (const float*)d_in[23];
    const float* conv2_w = (const float*)d_in[24];
    const float* conv2_b = (const float*)d_in[25];
    const float* temperature = (const float*)d_in[26];

    const int SMD = (2*DBUF)*4 + ATILE*2;   // 102912 + 9984 = 112896 -> 2 CTAs/SM
    cudaFuncSetAttribute(k_dilated_mma, cudaFuncAttributeMaxDynamicSharedMemorySize, SMD);

    k_misc<<<200, 256>>>(qkvl_w, qkvr_w, convQ_w, convQ_b,
                         dil0_w, dil1_w, dil2_w, dil0_b, dil1_b, dil2_b,
                         ln1_w, ln1_b, ln2_w, ln2_b, qkvl_b, qkvr_b);
    k_qkv<<<dim3(HWW/256, BB, 2), 288>>>(x_l, x_r);
    k_dw<<<dim3(HH/8, 72, 2*BB), 512>>>(dwl_w, dwl_b, dwr_w, dwr_b);
    k_dilated_mma<<<dim3(HH, BB), 256, SMD>>>();
    k_dots<<<dim3(16, BB*NH, 2), 256>>>();
    k_soft_m<<<4, 256>>>(temperature, conv1_w, conv2_w);
    k_epilogue<<<dim3(HWW/256, BB, 2), 256>>>(x_l, x_r, conv1_b, conv2_b, (float*)d_out);
}